// round 13
// baseline (speedup 1.0000x reference)
#include <cuda_runtime.h>
#include <cuda_bf16.h>
#include <cstdint>
#include <cstddef>
#include <math.h>

typedef unsigned long long ull;
typedef unsigned int u32;
typedef unsigned short u16;

// Problem constants
constexpr int Bc = 2048;
constexpr int Tc = 13;
constexpr int Hc = 256;
constexpr int Mc = Bc * Tc;      // 26624 rows for the input GEMMs
constexpr int K0P = 192;         // layer-0 K (188) padded to multiple of 16

// Scratch (device globals: allocation-free rule)
__device__ float g_gx[(size_t)2 * Mc * 768];    // [dir][b*T+t][768]
__device__ float g_hsum[(size_t)2 * Bc * Hc];   // [dir][b][256] summed over layers

// bf16 split operands for the tensor-core input GEMMs
__device__ __nv_bfloat16 g_x_hi[(size_t)Mc * K0P];
__device__ __nv_bfloat16 g_x_lo[(size_t)Mc * K0P];
constexpr size_t WIH_ELEMS = (size_t)1536 * K0P + (size_t)7 * 1536 * 512;
__device__ __nv_bfloat16 g_w_hi[WIH_ELEMS];
__device__ __nv_bfloat16 g_w_lo[WIH_ELEMS];
__device__ __nv_bfloat16 g_a_hi[(size_t)Mc * 512];   // layer outputs (next-layer A)
__device__ __nv_bfloat16 g_a_lo[(size_t)Mc * 512];

// W_hh pre-split bf16, packed per (l2, kchunk): [hi 768x16][lo 768x16], XOR-swizzled
// rows so ldmatrix phases are bank-conflict-free. One chunk = 49152 B contiguous.
constexpr int WCHUNK_E = 24576;              // elements per chunk (hi+lo)
constexpr int WCHUNK_B = WCHUNK_E * 2;       // 49152 bytes
__device__ __align__(128) __nv_bfloat16 g_whh[(size_t)16 * 16 * WCHUNK_E];

// ---------- math helpers ----------
__device__ __forceinline__ float sigmf(float x) { return 1.f / (1.f + expf(-x)); }
__device__ __forceinline__ float sigf(float x)  { return __fdividef(1.f, 1.f + __expf(-x)); }
__device__ __forceinline__ float tanhfast(float x) { return 2.f * sigf(2.f * x) - 1.f; }

__device__ __forceinline__ void split_bf(float v, u16& h, u16& l) {
    __nv_bfloat16 hb = __float2bfloat16(v);
    float r = v - __bfloat162float(hb);
    h = __bfloat16_as_ushort(hb);
    l = __bfloat16_as_ushort(__float2bfloat16(r));
}

// pack two fp32 -> bf16x2 in one op (lo = first arg)
__device__ __forceinline__ u32 cvt2bf(float lo, float hi) {
    u32 r; asm("cvt.rn.bf16x2.f32 %0, %1, %2;" : "=r"(r) : "f"(hi), "f"(lo)); return r;
}

// ---------- mma / smem helpers ----------
__device__ __forceinline__ u32 smem_u32(const void* p) {
    return (u32)__cvta_generic_to_shared(p);
}
__device__ __forceinline__ void ldsm_x4(u32& r0, u32& r1, u32& r2, u32& r3, u32 addr) {
    asm volatile("ldmatrix.sync.aligned.m8n8.x4.shared.b16 {%0,%1,%2,%3}, [%4];\n"
                 : "=r"(r0), "=r"(r1), "=r"(r2), "=r"(r3) : "r"(addr));
}
__device__ __forceinline__ void mma_bf16(float* d, const u32* a, const u32* b) {
    asm volatile("mma.sync.aligned.m16n8k16.row.col.f32.bf16.bf16.f32 "
                 "{%0,%1,%2,%3}, {%4,%5,%6,%7}, {%8,%9}, {%0,%1,%2,%3};\n"
                 : "+f"(d[0]), "+f"(d[1]), "+f"(d[2]), "+f"(d[3])
                 : "r"(a[0]), "r"(a[1]), "r"(a[2]), "r"(a[3]), "r"(b[0]), "r"(b[1]));
}
__device__ __forceinline__ void cp16(u32 dst, const void* src) {
    asm volatile("cp.async.cg.shared.global [%0], [%1], 16;" :: "r"(dst), "l"(src));
}
#define CP_COMMIT() asm volatile("cp.async.commit_group;\n" ::: "memory")
#define CP_WAIT2()  asm volatile("cp.async.wait_group 2;\n" ::: "memory")

// ---------- mbarrier + bulk-copy helpers ----------
__device__ __forceinline__ void mbar_init(u32 mbar, u32 cnt) {
    asm volatile("mbarrier.init.shared.b64 [%0], %1;" :: "r"(mbar), "r"(cnt) : "memory");
}
__device__ __forceinline__ void mbar_expect(u32 mbar, u32 bytes) {
    asm volatile("mbarrier.arrive.expect_tx.shared.b64 _, [%0], %1;"
                 :: "r"(mbar), "r"(bytes) : "memory");
}
__device__ __forceinline__ void mbar_arrive(u32 mbar) {
    asm volatile("mbarrier.arrive.shared.b64 _, [%0];" :: "r"(mbar) : "memory");
}
__device__ __forceinline__ void bulk_g2s(u32 dst, const void* src, u32 bytes, u32 mbar) {
    asm volatile("cp.async.bulk.shared::cta.global.mbarrier::complete_tx::bytes "
                 "[%0], [%1], %2, [%3];"
                 :: "r"(dst), "l"(src), "r"(bytes), "r"(mbar) : "memory");
}
__device__ __forceinline__ void mbar_wait(u32 mbar, u32 parity) {
    asm volatile(
        "{\n\t"
        ".reg .pred P;\n\t"
        "WL%=:\n\t"
        "mbarrier.try_wait.parity.acquire.cta.shared::cta.b64 P, [%0], %1, 0x989680;\n\t"
        "@P bra WD%=;\n\t"
        "bra WL%=;\n\t"
        "WD%=:\n\t"
        "}"
        :: "r"(mbar), "r"(parity) : "memory");
}

// ---------- prep kernel 1: convert x + W_ih -> bf16 hi/lo ----------
__global__ void convert_inputs_kernel(const float* __restrict__ x,
                                      const float* __restrict__ W0,
                                      const float* __restrict__ Wr) {
    size_t i = (size_t)blockIdx.x * blockDim.x + threadIdx.x;
    const size_t NX = (size_t)Mc * K0P;
    if (i < NX) {
        int row = (int)(i / K0P), col = (int)(i - (size_t)row * K0P);
        float v = (col < 188) ? x[(size_t)row * 188 + col] : 0.f;
        u16 h, l;
        split_bf(v, h, l);
        g_x_hi[i] = __ushort_as_bfloat16(h);
        g_x_lo[i] = __ushort_as_bfloat16(l);
    } else if (i < NX + WIH_ELEMS) {
        size_t j = i - NX;
        float v;
        if (j < (size_t)1536 * K0P) {
            int row = (int)(j / K0P), col = (int)(j - (size_t)row * K0P);
            v = (col < 188) ? W0[(size_t)row * 188 + col] : 0.f;
        } else {
            v = Wr[j - (size_t)1536 * K0P];
        }
        u16 h, l;
        split_bf(v, h, l);
        g_w_hi[j] = __ushort_as_bfloat16(h);
        g_w_lo[j] = __ushort_as_bfloat16(l);
    }
}

// ---------- prep kernel 2: convert W_hh (swizzled chunks) ----------
constexpr size_t WHH_ELEMS = (size_t)16 * 768 * 256;
__global__ void convert_whh_kernel(const float* __restrict__ Whh) {
    size_t i = (size_t)blockIdx.x * blockDim.x + threadIdx.x;
    if (i >= WHH_ELEMS) return;
    size_t l2 = i / ((size_t)768 * 256);
    size_t rem = i - l2 * 768 * 256;
    int n = (int)(rem / 256), k = (int)(rem % 256);
    float v = Whh[i];
    u16 h, l;
    split_bf(v, h, l);
    int kk = k & 15;
    // XOR swizzle: 16B-half index ^= (n>>2)&1  -> conflict-free ldmatrix phases
    u32 swb = (((u32)(kk >> 3) ^ (u32)((n >> 2) & 1)) << 4);
    size_t byte_in = (size_t)n * 32 + swb + (size_t)(kk & 7) * 2;
    size_t o = ((size_t)l2 * 16 + (size_t)(k >> 4)) * WCHUNK_E + byte_in / 2;
    g_whh[o] = __ushort_as_bfloat16(h);
    g_whh[o + 12288] = __ushort_as_bfloat16(l);
}

// ---------- prep kernel 3: zero hsum (separate so ncu launch #6 = gemm layer 1) ----------
__global__ void zero_hsum_kernel() {
    int i = blockIdx.x * blockDim.x + threadIdx.x;
    if (i < 2 * Bc * Hc) g_hsum[i] = 0.f;
}

// ---------- input GEMM (tensor cores, 3xBF16 split, cp.async 4-stage) ----------
constexpr int GPITCH = 24;                  // bf16 elems per smem row (48B)
constexpr int GTSZ = 128 * GPITCH;          // elems per (stage,op) tile
constexpr int GSTAGES = 4;
constexpr int GEMM_SMEM = GSTAGES * 4 * GTSZ * 2; // 98304 B

__global__ void __launch_bounds__(256, 2) gemm_gx_mma(int layer, const float* __restrict__ bias) {
    extern __shared__ __nv_bfloat16 sm[];

    const __nv_bfloat16 *Ahi, *Alo, *Whi, *Wlo;
    int K;
    if (layer == 0) {
        Ahi = g_x_hi; Alo = g_x_lo; Whi = g_w_hi; Wlo = g_w_lo; K = K0P;
    } else {
        size_t wo = (size_t)1536 * K0P + (size_t)(layer - 1) * 1536 * 512;
        Ahi = g_a_hi; Alo = g_a_lo; Whi = g_w_hi + wo; Wlo = g_w_lo + wo; K = 512;
    }

    const int tid = threadIdx.x;
    const int m0 = blockIdx.y * 128;
    const int n0 = blockIdx.x * 128;

    const int lrow = tid >> 1;
    const int lhalf = tid & 1;
    const size_t aoff = (size_t)(m0 + lrow) * K + lhalf * 8;
    const size_t boff = (size_t)(n0 + lrow) * K + lhalf * 8;
    const u32 smoffB = (u32)(lrow * GPITCH + lhalf * 8) * 2;   // bytes

    const int wid = tid >> 5, lane = tid & 31;
    const int wm = (wid & 1) << 6;
    const int wn = (wid >> 1) << 5;

    float acc[4][4][4];
#pragma unroll
    for (int mi = 0; mi < 4; mi++)
#pragma unroll
        for (int ni = 0; ni < 4; ni++)
#pragma unroll
            for (int e = 0; e < 4; e++) acc[mi][ni][e] = 0.f;

    const int lr = lane & 15, lh = lane >> 4;
    int aoffs[4], boffs[2];
#pragma unroll
    for (int mi = 0; mi < 4; mi++)
        aoffs[mi] = ((wm + mi * 16 + lr) * GPITCH + lh * 8) * 2;
#pragma unroll
    for (int p = 0; p < 2; p++)
        boffs[p] = ((wn + p * 16 + lr) * GPITCH + lh * 8) * 2;

    const u32 smb = smem_u32(sm);
    const int nk = K >> 4;
    constexpr u32 STB = 4 * GTSZ * 2;       // bytes per stage

    auto load_chunk = [&](int kc, int s) {
        const size_t ka = (size_t)kc * 16;
        const u32 d = smb + (u32)s * STB + smoffB;
        cp16(d + 0 * GTSZ * 2, Ahi + aoff + ka);
        cp16(d + 1 * GTSZ * 2, Alo + aoff + ka);
        cp16(d + 2 * GTSZ * 2, Whi + boff + ka);
        cp16(d + 3 * GTSZ * 2, Wlo + boff + ka);
    };

    // prologue: 3 chunks in flight
#pragma unroll
    for (int s = 0; s < GSTAGES - 1; s++) { load_chunk(s, s); CP_COMMIT(); }

#pragma unroll 1
    for (int kc = 0; kc < nk; kc++) {
        CP_WAIT2();                          // oldest (stage kc) complete; 2 still in flight
        __syncthreads();                     // all warps done reading stage (kc+3)&3 last round
        if (kc + GSTAGES - 1 < nk) { load_chunk(kc + GSTAGES - 1, (kc + GSTAGES - 1) & 3); CP_COMMIT(); }

        const u32 sbase = smb + (u32)(kc & 3) * STB;
        u32 ahi[4][4], alo[4][4], bhi[4][2], blo[4][2];
#pragma unroll
        for (int mi = 0; mi < 4; mi++) {
            ldsm_x4(ahi[mi][0], ahi[mi][1], ahi[mi][2], ahi[mi][3], sbase + aoffs[mi]);
            ldsm_x4(alo[mi][0], alo[mi][1], alo[mi][2], alo[mi][3],
                    sbase + aoffs[mi] + GTSZ * 2);
        }
#pragma unroll
        for (int p = 0; p < 2; p++) {
            u32 t0, t1, t2, t3;
            ldsm_x4(t0, t1, t2, t3, sbase + boffs[p] + 2 * GTSZ * 2);
            bhi[2 * p][0] = t0; bhi[2 * p + 1][0] = t1;
            bhi[2 * p][1] = t2; bhi[2 * p + 1][1] = t3;
            ldsm_x4(t0, t1, t2, t3, sbase + boffs[p] + 3 * GTSZ * 2);
            blo[2 * p][0] = t0; blo[2 * p + 1][0] = t1;
            blo[2 * p][1] = t2; blo[2 * p + 1][1] = t3;
        }

#pragma unroll
        for (int mi = 0; mi < 4; mi++)
#pragma unroll
            for (int ni = 0; ni < 4; ni++) {
                mma_bf16(acc[mi][ni], ahi[mi], bhi[ni]);
                mma_bf16(acc[mi][ni], ahi[mi], blo[ni]);
                mma_bf16(acc[mi][ni], alo[mi], bhi[ni]);
            }
    }

    const int cr = lane >> 2;
    const int cc = (lane & 3) << 1;
#pragma unroll
    for (int ni = 0; ni < 4; ni++) {
        const int n = n0 + wn + ni * 8 + cc;
        const int d = (n >= 768) ? 1 : 0;
        const int g = n - d * 768;
        const float bx = bias[n], by = bias[n + 1];
#pragma unroll
        for (int mi = 0; mi < 4; mi++) {
            const int m = m0 + wm + mi * 16 + cr;
            float* p0 = g_gx + ((size_t)d * Mc + m) * 768 + g;
            float2 v0 = make_float2(acc[mi][ni][0] + bx, acc[mi][ni][1] + by);
            float2 v1 = make_float2(acc[mi][ni][2] + bx, acc[mi][ni][3] + by);
            *(float2*)p0 = v0;
            *(float2*)(p0 + 8 * 768) = v1;
        }
    }
}

// ---------- tensor-core GRU recurrence (decoupled mbarrier pipeline) ----------
constexpr int RROWS = 32;
constexpr int RTHREADS = 512;
constexpr int APITCH = 264;                 // bf16 elems per h-smem row
constexpr int NSTAGE = 3;
constexpr int HSM_E = 2 * RROWS * APITCH;   // h hi+lo elems
constexpr int MBAR_OFF = NSTAGE * WCHUNK_B + HSM_E * 2;        // byte offset of mbars
constexpr int RECUR_SMEM = MBAR_OFF + 64;                      // 181312 B

__global__ void __launch_bounds__(RTHREADS, 1) gru_recur_mma(
    const float* __restrict__ bhh_all, int layer)
{
    extern __shared__ __nv_bfloat16 rsm[];
    const int tid = threadIdx.x;
    const int w = tid >> 5, lane = tid & 31;
    const int dir = blockIdx.y;
    const int b0 = blockIdx.x * RROWS;
    const int l2 = layer * 2 + dir;
    const float* bhh = bhh_all + (size_t)l2 * 768;
    const float* gxd = g_gx + (size_t)dir * Mc * 768;
    const __nv_bfloat16* wsrc = g_whh + (size_t)l2 * 16 * WCHUNK_E;

    __nv_bfloat16* hhi = rsm + NSTAGE * WCHUNK_E;
    __nv_bfloat16* hlo = hhi + RROWS * APITCH;
    const u32 smb = smem_u32(rsm);
    const u32 hhib = smem_u32(hhi);
    const u32 hlob = smem_u32(hlo);
    const u32 mb_full  = smb + (u32)MBAR_OFF;        // 3 x 8B
    const u32 mb_empty = mb_full + 24;               // 3 x 8B

    for (int i = tid; i < HSM_E; i += RTHREADS)
        hhi[i] = __ushort_as_bfloat16(0);
    if (tid == 0) {
#pragma unroll
        for (int s = 0; s < NSTAGE; s++) {
            mbar_init(mb_full + s * 8, 1);
            mbar_init(mb_empty + s * 8, 16);
        }
    }
    __syncthreads();
    // pre-charge: every warp marks all stages empty (completes empty phase 0)
    if (lane == 0) {
#pragma unroll
        for (int s = 0; s < NSTAGE; s++) mbar_arrive(mb_empty + s * 8);
    }
    __syncthreads();

    constexpr int NCHUNK = Tc * 16;          // 208 chunk iterations per layer
    auto issue = [&](int cc_) {
        if (cc_ < NCHUNK) {
            const int s2 = cc_ % NSTAGE;
            mbar_wait(mb_empty + s2 * 8, (u32)((cc_ / NSTAGE) & 1));
            mbar_expect(mb_full + s2 * 8, WCHUNK_B);
            bulk_g2s(smb + (u32)s2 * WCHUNK_B, wsrc + (size_t)(cc_ & 15) * WCHUNK_E,
                     WCHUNK_B, mb_full + s2 * 8);
        }
    };
    if (tid == 0) { issue(0); issue(1); }

    const int c2 = (lane & 3) << 1;   // col pair base within n8
    const int r1 = lane >> 2;         // row within m8 group
    const int lr = lane & 15, lh = lane >> 4;
    const u32 swz = (u32)(((lr >> 2) & 1) << 4);   // B ldsm de-swizzle

    // precomputed ldsm base addresses (chunk loop adds stage/kc offsets only)
    u32 aoBase[2], bOff[3];
#pragma unroll
    for (int mt = 0; mt < 2; mt++)
        aoBase[mt] = (u32)(((mt * 16 + lr) * APITCH + lh * 8) * 2);
#pragma unroll
    for (int g = 0; g < 3; g++)
        bOff[g] = (u32)((g * 256 + w * 16 + lr) * 32) + (((u32)(lh << 4)) ^ swz);

    // recurrent biases for this thread's columns (per gate, per n8 sub-tile)
    float2 bh[3][2];
#pragma unroll
    for (int g = 0; g < 3; g++)
#pragma unroll
        for (int sub = 0; sub < 2; sub++)
            bh[g][sub] = *(const float2*)&bhh[g * 256 + w * 16 + sub * 8 + c2];

    // h (fp32) in C-fragment layout registers across steps
    float hprev[2][2][4];
#pragma unroll
    for (int mt = 0; mt < 2; mt++)
#pragma unroll
        for (int sub = 0; sub < 2; sub++)
#pragma unroll
            for (int e = 0; e < 4; e++) hprev[mt][sub][e] = 0.f;

    int c = 0;   // global chunk counter across steps

#pragma unroll 1
    for (int step = 0; step < Tc; step++) {
        const int tg = dir ? (Tc - 1 - step) : step;

        float acc[2][6][4];
#pragma unroll
        for (int mt = 0; mt < 2; mt++)
#pragma unroll
            for (int t = 0; t < 6; t++)
#pragma unroll
                for (int e = 0; e < 4; e++) acc[mt][t][e] = 0.f;

#pragma unroll 1
        for (int kc = 0; kc < 16; kc++) {
            if (tid == 0) issue(c + 2);
            const int s = c % NSTAGE;
            mbar_wait(mb_full + s * 8, (u32)((c / NSTAGE) & 1));

            // A fragments from h smem (hi/lo), 2 m16 tiles (broadcast to all warps)
            const u32 akk = (u32)(kc * 32);
            u32 ahi[2][4], alo[2][4];
#pragma unroll
            for (int mt = 0; mt < 2; mt++) {
                ldsm_x4(ahi[mt][0], ahi[mt][1], ahi[mt][2], ahi[mt][3], hhib + aoBase[mt] + akk);
                ldsm_x4(alo[mt][0], alo[mt][1], alo[mt][2], alo[mt][3], hlob + aoBase[mt] + akk);
            }

            const u32 sbase = smb + (u32)s * WCHUNK_B;
            u32 bhr[3][2][2], blr[3][2][2];
#pragma unroll
            for (int g = 0; g < 3; g++) {
                const u32 ad = sbase + bOff[g];
                u32 t0, t1, t2, t3;
                ldsm_x4(t0, t1, t2, t3, ad);
                bhr[g][0][0] = t0; bhr[g][1][0] = t1; bhr[g][0][1] = t2; bhr[g][1][1] = t3;
                ldsm_x4(t0, t1, t2, t3, ad + 24576);   // lo half of chunk
                blr[g][0][0] = t0; blr[g][1][0] = t1; blr[g][0][1] = t2; blr[g][1][1] = t3;
            }
            if (lane == 0) mbar_arrive(mb_empty + s * 8);   // this warp done with stage s

#pragma unroll
            for (int g = 0; g < 3; g++)
#pragma unroll
                for (int mt = 0; mt < 2; mt++)
#pragma unroll
                    for (int nt = 0; nt < 2; nt++) {
                        float* d = acc[mt][g * 2 + nt];
                        mma_bf16(d, ahi[mt], bhr[g][nt]);
                        mma_bf16(d, ahi[mt], blr[g][nt]);
                        mma_bf16(d, alo[mt], bhr[g][nt]);
                    }
            c++;
        }

        // gate math entirely in registers
#pragma unroll
        for (int mt = 0; mt < 2; mt++)
#pragma unroll
            for (int sub = 0; sub < 2; sub++) {
                const int jc = w * 16 + sub * 8 + c2;
                const float2 br = bh[0][sub], bz = bh[1][sub], bn = bh[2][sub];
#pragma unroll
                for (int half = 0; half < 2; half++) {
                    const int row = mt * 16 + r1 + half * 8;
                    const int b = b0 + row;
                    const float* gxrow = gxd + ((size_t)b * Tc + tg) * 768 + jc;
                    const float2 xr = *(const float2*)gxrow;
                    const float2 xz = *(const float2*)(gxrow + 256);
                    const float2 xn = *(const float2*)(gxrow + 512);
                    const int e = half * 2;
                    float rx = sigf(xr.x + acc[mt][sub][e]     + br.x);
                    float ry = sigf(xr.y + acc[mt][sub][e + 1] + br.y);
                    float zx = sigf(xz.x + acc[mt][2 + sub][e]     + bz.x);
                    float zy = sigf(xz.y + acc[mt][2 + sub][e + 1] + bz.y);
                    float nx = tanhfast(xn.x + rx * (acc[mt][4 + sub][e]     + bn.x));
                    float ny = tanhfast(xn.y + ry * (acc[mt][4 + sub][e + 1] + bn.y));
                    float hx = (1.f - zx) * nx + zx * hprev[mt][sub][e];
                    float hy = (1.f - zy) * ny + zy * hprev[mt][sub][e + 1];
                    hprev[mt][sub][e] = hx;
                    hprev[mt][sub][e + 1] = hy;
                }
            }

        __syncthreads();   // all warps done reading h smem this step

        // write new h: smem (A layout) + global next-layer operands (+ hsum)
#pragma unroll
        for (int mt = 0; mt < 2; mt++)
#pragma unroll
            for (int sub = 0; sub < 2; sub++) {
                const int jc = w * 16 + sub * 8 + c2;
#pragma unroll
                for (int half = 0; half < 2; half++) {
                    const int row = mt * 16 + r1 + half * 8;
                    const int b = b0 + row;
                    const int e = half * 2;
                    const float hx = hprev[mt][sub][e];
                    const float hy = hprev[mt][sub][e + 1];
                    const u32 ph = cvt2bf(hx, hy);
                    const float hfx = __uint_as_float(ph << 16);
                    const float hfy = __uint_as_float(ph & 0xffff0000u);
                    const u32 pl = cvt2bf(hx - hfx, hy - hfy);
                    *(u32*)(hhi + row * APITCH + jc) = ph;
                    *(u32*)(hlo + row * APITCH + jc) = pl;
                    const size_t ob = ((size_t)b * Tc + tg) * 512 + dir * 256 + jc;
                    *(u32*)(g_a_hi + ob) = ph;
                    *(u32*)(g_a_lo + ob) = pl;
                    if (step == Tc - 1) {
                        float* hp = g_hsum + ((size_t)dir * Bc + b) * 256 + jc;
                        float2 cur = *(const float2*)hp;
                        cur.x += hx; cur.y += hy;
                        *(float2*)hp = cur;
                    }
                }
            }
        __syncthreads();   // h writes visible before next step's A ldsm
    }
}

// ---------- head: mean over 16 finals -> silu MLP -> scalar ----------
__global__ void head_kernel(const float* __restrict__ W1, const float* __restrict__ b1,
                            const float* __restrict__ W2, const float* __restrict__ b2,
                            const float* __restrict__ Wc, const float* __restrict__ bc,
                            float* __restrict__ out)
{
    const int b = blockIdx.x;
    const int tid = threadIdx.x;   // 64 threads
    __shared__ float hs[256];
    __shared__ float s1[64];
    for (int i = tid; i < 256; i += 64)
        hs[i] = (g_hsum[(size_t)b * 256 + i] + g_hsum[(size_t)(Bc + b) * 256 + i]) * (1.f / 16.f);
    __syncthreads();
    float a1 = b1[tid];
    const float* w1r = W1 + (size_t)tid * 256;
#pragma unroll 4
    for (int k = 0; k < 256; k++) a1 += hs[k] * w1r[k];
    s1[tid] = a1 * sigmf(a1);
    __syncthreads();
    if (tid < 32) {
        float a2 = b2[tid];
        const float* w2r = W2 + (size_t)tid * 64;
#pragma unroll
        for (int k = 0; k < 64; k++) a2 += s1[k] * w2r[k];
        float y = a2 * sigmf(a2);
        float v = y * Wc[tid];
#pragma unroll
        for (int o = 16; o > 0; o >>= 1) v += __shfl_down_sync(0xffffffffu, v, o);
        if (tid == 0) out[b] = v + bc[0];
    }
}

// ---------- launch ----------
extern "C" void kernel_launch(void* const* d_in, const int* in_sizes, int n_in,
                              void* d_out, int out_size) {
    (void)in_sizes; (void)n_in; (void)out_size;
    const float* x         = (const float*)d_in[0];
    const float* W_ih0     = (const float*)d_in[1];
    const float* W_ih_rest = (const float*)d_in[2];
    const float* W_hh      = (const float*)d_in[3];
    const float* b_ih      = (const float*)d_in[4];
    const float* b_hh      = (const float*)d_in[5];
    const float* W1        = (const float*)d_in[6];
    const float* b1        = (const float*)d_in[7];
    const float* W2        = (const float*)d_in[8];
    const float* b2        = (const float*)d_in[9];
    const float* Wc        = (const float*)d_in[10];
    const float* bc        = (const float*)d_in[11];
    float* out = (float*)d_out;

    cudaFuncSetAttribute(gemm_gx_mma,
                         cudaFuncAttributeMaxDynamicSharedMemorySize, GEMM_SMEM);
    cudaFuncSetAttribute(gru_recur_mma,
                         cudaFuncAttributeMaxDynamicSharedMemorySize, RECUR_SMEM);

    // 3 prep launches so ncu (-s 5 -c 1) captures launch #6 = gemm_gx_mma layer 1.
    const size_t NPREP1 = (size_t)Mc * K0P + WIH_ELEMS;
    convert_inputs_kernel<<<(int)((NPREP1 + 255) / 256), 256>>>(x, W_ih0, W_ih_rest);
    convert_whh_kernel<<<(int)((WHH_ELEMS + 255) / 256), 256>>>(W_hh);
    zero_hsum_kernel<<<(2 * Bc * Hc + 255) / 256, 256>>>();

    dim3 ggrid(12, 208);            // N/128, M/128
    dim3 rgrid(Bc / RROWS, 2);      // 64 x 2 dirs

    for (int l = 0; l < 8; l++) {
        gemm_gx_mma<<<ggrid, 256, GEMM_SMEM>>>(l, b_ih + (size_t)l * 1536);
        gru_recur_mma<<<rgrid, RTHREADS, RECUR_SMEM>>>(b_hh, l);
    }

    head_kernel<<<Bc, 64>>>(W1, b1, W2, b2, Wc, bc, out);
}

// round 14
// speedup vs baseline: 1.4140x; 1.4140x over previous
#include <cuda_runtime.h>
#include <cuda_fp16.h>
#include <cstdint>
#include <cstddef>
#include <math.h>

typedef unsigned long long ull;
typedef unsigned int u32;
typedef unsigned short u16;

// Problem constants
constexpr int Bc = 2048;
constexpr int Tc = 13;
constexpr int Hc = 256;
constexpr int Mc = Bc * Tc;      // 26624 rows for the input GEMMs
constexpr int K0P = 192;         // layer-0 K (188) padded to multiple of 16

// Scratch (device globals: allocation-free rule)
__device__ float g_gx[(size_t)2 * Mc * 768];    // [dir][b*T+t][768]
__device__ float g_hsum[(size_t)2 * Bc * Hc];   // [dir][b][256] summed over layers

// fp16 operands: activations single-precision fp16 (fresh rounding each step,
// incoherent error), weights split hi+lo fp16 (error 2^-22, negligible).
__device__ __half g_x[(size_t)Mc * K0P];
constexpr size_t WIH_ELEMS = (size_t)1536 * K0P + (size_t)7 * 1536 * 512;
__device__ __half g_w_hi[WIH_ELEMS];
__device__ __half g_w_lo[WIH_ELEMS];
__device__ __half g_a[(size_t)Mc * 512];        // layer outputs (next-layer A)

// W_hh fp16, packed per (l2, kchunk): [hi 768x16][lo 768x16], XOR-swizzled rows
// so ldmatrix phases are bank-conflict-free. One chunk = 49152 B contiguous.
constexpr int WCHUNK_E = 24576;              // elements per chunk (hi+lo)
constexpr int WCHUNK_B = WCHUNK_E * 2;       // 49152 bytes
__device__ __align__(128) __half g_whh[(size_t)16 * 16 * WCHUNK_E];

// ---------- math helpers ----------
__device__ __forceinline__ float sigmf(float x) { return 1.f / (1.f + expf(-x)); }
__device__ __forceinline__ float sigf(float x)  { return __fdividef(1.f, 1.f + __expf(-x)); }
__device__ __forceinline__ float tanhfast(float x) { return 2.f * sigf(2.f * x) - 1.f; }

__device__ __forceinline__ void split_h16(float v, u16& h, u16& l) {
    __half hh = __float2half_rn(v);
    float r = v - __half2float(hh);
    h = __half_as_ushort(hh);
    l = __half_as_ushort(__float2half_rn(r));
}

// pack two fp32 -> f16x2 in one value (x = low half)
__device__ __forceinline__ u32 cvt2h(float x, float y) {
    __half2 p = __floats2half2_rn(x, y);
    return *reinterpret_cast<u32*>(&p);
}

// ---------- mma / smem helpers ----------
__device__ __forceinline__ u32 smem_u32(const void* p) {
    return (u32)__cvta_generic_to_shared(p);
}
__device__ __forceinline__ void ldsm_x4(u32& r0, u32& r1, u32& r2, u32& r3, u32 addr) {
    asm volatile("ldmatrix.sync.aligned.m8n8.x4.shared.b16 {%0,%1,%2,%3}, [%4];\n"
                 : "=r"(r0), "=r"(r1), "=r"(r2), "=r"(r3) : "r"(addr));
}
__device__ __forceinline__ void mma_f16(float* d, const u32* a, const u32* b) {
    asm volatile("mma.sync.aligned.m16n8k16.row.col.f32.f16.f16.f32 "
                 "{%0,%1,%2,%3}, {%4,%5,%6,%7}, {%8,%9}, {%0,%1,%2,%3};\n"
                 : "+f"(d[0]), "+f"(d[1]), "+f"(d[2]), "+f"(d[3])
                 : "r"(a[0]), "r"(a[1]), "r"(a[2]), "r"(a[3]), "r"(b[0]), "r"(b[1]));
}
__device__ __forceinline__ void cp16(u32 dst, const void* src) {
    asm volatile("cp.async.cg.shared.global [%0], [%1], 16;" :: "r"(dst), "l"(src));
}
#define CP_COMMIT() asm volatile("cp.async.commit_group;\n" ::: "memory")
#define CP_WAIT2()  asm volatile("cp.async.wait_group 2;\n" ::: "memory")

// ---------- mbarrier + bulk-copy helpers ----------
__device__ __forceinline__ void mbar_init(u32 mbar, u32 cnt) {
    asm volatile("mbarrier.init.shared.b64 [%0], %1;" :: "r"(mbar), "r"(cnt) : "memory");
}
__device__ __forceinline__ void mbar_expect(u32 mbar, u32 bytes) {
    asm volatile("mbarrier.arrive.expect_tx.shared.b64 _, [%0], %1;"
                 :: "r"(mbar), "r"(bytes) : "memory");
}
__device__ __forceinline__ void mbar_arrive(u32 mbar) {
    asm volatile("mbarrier.arrive.shared.b64 _, [%0];" :: "r"(mbar) : "memory");
}
__device__ __forceinline__ void bulk_g2s(u32 dst, const void* src, u32 bytes, u32 mbar) {
    asm volatile("cp.async.bulk.shared::cta.global.mbarrier::complete_tx::bytes "
                 "[%0], [%1], %2, [%3];"
                 :: "r"(dst), "l"(src), "r"(bytes), "r"(mbar) : "memory");
}
__device__ __forceinline__ void mbar_wait(u32 mbar, u32 parity) {
    asm volatile(
        "{\n\t"
        ".reg .pred P;\n\t"
        "WL%=:\n\t"
        "mbarrier.try_wait.parity.acquire.cta.shared::cta.b64 P, [%0], %1, 0x989680;\n\t"
        "@P bra WD%=;\n\t"
        "bra WL%=;\n\t"
        "WD%=:\n\t"
        "}"
        :: "r"(mbar), "r"(parity) : "memory");
}

// ---------- prep kernel 1: convert x (single fp16) + W_ih (split fp16) ----------
__global__ void convert_inputs_kernel(const float* __restrict__ x,
                                      const float* __restrict__ W0,
                                      const float* __restrict__ Wr) {
    size_t i = (size_t)blockIdx.x * blockDim.x + threadIdx.x;
    const size_t NX = (size_t)Mc * K0P;
    if (i < NX) {
        int row = (int)(i / K0P), col = (int)(i - (size_t)row * K0P);
        float v = (col < 188) ? x[(size_t)row * 188 + col] : 0.f;
        g_x[i] = __float2half_rn(v);
    } else if (i < NX + WIH_ELEMS) {
        size_t j = i - NX;
        float v;
        if (j < (size_t)1536 * K0P) {
            int row = (int)(j / K0P), col = (int)(j - (size_t)row * K0P);
            v = (col < 188) ? W0[(size_t)row * 188 + col] : 0.f;
        } else {
            v = Wr[j - (size_t)1536 * K0P];
        }
        u16 h, l;
        split_h16(v, h, l);
        g_w_hi[j] = __ushort_as_half(h);
        g_w_lo[j] = __ushort_as_half(l);
    }
}

// ---------- prep kernel 2: convert W_hh (swizzled fp16 hi/lo chunks) ----------
constexpr size_t WHH_ELEMS = (size_t)16 * 768 * 256;
__global__ void convert_whh_kernel(const float* __restrict__ Whh) {
    size_t i = (size_t)blockIdx.x * blockDim.x + threadIdx.x;
    if (i >= WHH_ELEMS) return;
    size_t l2 = i / ((size_t)768 * 256);
    size_t rem = i - l2 * 768 * 256;
    int n = (int)(rem / 256), k = (int)(rem % 256);
    float v = Whh[i];
    u16 h, l;
    split_h16(v, h, l);
    int kk = k & 15;
    // XOR swizzle: 16B-half index ^= (n>>2)&1  -> conflict-free ldmatrix phases
    u32 swb = (((u32)(kk >> 3) ^ (u32)((n >> 2) & 1)) << 4);
    size_t byte_in = (size_t)n * 32 + swb + (size_t)(kk & 7) * 2;
    size_t o = ((size_t)l2 * 16 + (size_t)(k >> 4)) * WCHUNK_E + byte_in / 2;
    g_whh[o] = __ushort_as_half(h);
    g_whh[o + 12288] = __ushort_as_half(l);
}

// ---------- prep kernels 3+4: zero hsum split in two (launch-count padding so
// ncu's -s 5 -c 1 capture lands on gru_recur_mma layer 0) ----------
__global__ void zero_hsum_a() {
    int i = blockIdx.x * blockDim.x + threadIdx.x;
    if (i < Bc * Hc) g_hsum[i] = 0.f;
}
__global__ void zero_hsum_b() {
    int i = blockIdx.x * blockDim.x + threadIdx.x;
    if (i < Bc * Hc) g_hsum[Bc * Hc + i] = 0.f;
}

// ---------- input GEMM (tensor cores, fp16 2-term, cp.async 4-stage) ----------
constexpr int GPITCH = 24;                  // fp16 elems per smem row (48B)
constexpr int GTSZ = 128 * GPITCH;          // elems per (stage,op) tile
constexpr int GSTAGES = 4;
constexpr int GEMM_SMEM = GSTAGES * 3 * GTSZ * 2; // 73728 B

__global__ void __launch_bounds__(256, 2) gemm_gx_mma(int layer, const float* __restrict__ bias) {
    extern __shared__ __half sm[];

    const __half *A, *Whi, *Wlo;
    int K;
    if (layer == 0) {
        A = g_x; Whi = g_w_hi; Wlo = g_w_lo; K = K0P;
    } else {
        size_t wo = (size_t)1536 * K0P + (size_t)(layer - 1) * 1536 * 512;
        A = g_a; Whi = g_w_hi + wo; Wlo = g_w_lo + wo; K = 512;
    }

    const int tid = threadIdx.x;
    const int m0 = blockIdx.y * 128;
    const int n0 = blockIdx.x * 128;

    const int lrow = tid >> 1;
    const int lhalf = tid & 1;
    const size_t aoff = (size_t)(m0 + lrow) * K + lhalf * 8;
    const size_t boff = (size_t)(n0 + lrow) * K + lhalf * 8;
    const u32 smoffB = (u32)(lrow * GPITCH + lhalf * 8) * 2;   // bytes

    const int wid = tid >> 5, lane = tid & 31;
    const int wm = (wid & 1) << 6;
    const int wn = (wid >> 1) << 5;

    float acc[4][4][4];
#pragma unroll
    for (int mi = 0; mi < 4; mi++)
#pragma unroll
        for (int ni = 0; ni < 4; ni++)
#pragma unroll
            for (int e = 0; e < 4; e++) acc[mi][ni][e] = 0.f;

    const int lr = lane & 15, lh = lane >> 4;
    int aoffs[4], boffs[2];
#pragma unroll
    for (int mi = 0; mi < 4; mi++)
        aoffs[mi] = ((wm + mi * 16 + lr) * GPITCH + lh * 8) * 2;
#pragma unroll
    for (int p = 0; p < 2; p++)
        boffs[p] = ((wn + p * 16 + lr) * GPITCH + lh * 8) * 2;

    const u32 smb = smem_u32(sm);
    const int nk = K >> 4;
    constexpr u32 STB = 3 * GTSZ * 2;       // bytes per stage (A, Whi, Wlo)

    auto load_chunk = [&](int kc, int s) {
        const size_t ka = (size_t)kc * 16;
        const u32 d = smb + (u32)s * STB + smoffB;
        cp16(d + 0 * GTSZ * 2, A   + aoff + ka);
        cp16(d + 1 * GTSZ * 2, Whi + boff + ka);
        cp16(d + 2 * GTSZ * 2, Wlo + boff + ka);
    };

    // prologue: 3 chunks in flight
#pragma unroll
    for (int s = 0; s < GSTAGES - 1; s++) { load_chunk(s, s); CP_COMMIT(); }

#pragma unroll 1
    for (int kc = 0; kc < nk; kc++) {
        CP_WAIT2();                          // oldest (stage kc) complete; 2 in flight
        __syncthreads();                     // all warps done reading recycled stage
        if (kc + GSTAGES - 1 < nk) { load_chunk(kc + GSTAGES - 1, (kc + GSTAGES - 1) & 3); CP_COMMIT(); }

        const u32 sbase = smb + (u32)(kc & 3) * STB;
        u32 a[4][4], bhi[4][2], blo[4][2];
#pragma unroll
        for (int mi = 0; mi < 4; mi++)
            ldsm_x4(a[mi][0], a[mi][1], a[mi][2], a[mi][3], sbase + aoffs[mi]);
#pragma unroll
        for (int p = 0; p < 2; p++) {
            u32 t0, t1, t2, t3;
            ldsm_x4(t0, t1, t2, t3, sbase + boffs[p] + 1 * GTSZ * 2);
            bhi[2 * p][0] = t0; bhi[2 * p + 1][0] = t1;
            bhi[2 * p][1] = t2; bhi[2 * p + 1][1] = t3;
            ldsm_x4(t0, t1, t2, t3, sbase + boffs[p] + 2 * GTSZ * 2);
            blo[2 * p][0] = t0; blo[2 * p + 1][0] = t1;
            blo[2 * p][1] = t2; blo[2 * p + 1][1] = t3;
        }

#pragma unroll
        for (int mi = 0; mi < 4; mi++)
#pragma unroll
            for (int ni = 0; ni < 4; ni++) {
                mma_f16(acc[mi][ni], a[mi], bhi[ni]);
                mma_f16(acc[mi][ni], a[mi], blo[ni]);
            }
    }

    const int cr = lane >> 2;
    const int cc = (lane & 3) << 1;
#pragma unroll
    for (int ni = 0; ni < 4; ni++) {
        const int n = n0 + wn + ni * 8 + cc;
        const int d = (n >= 768) ? 1 : 0;
        const int g = n - d * 768;
        const float bx = bias[n], by = bias[n + 1];
#pragma unroll
        for (int mi = 0; mi < 4; mi++) {
            const int m = m0 + wm + mi * 16 + cr;
            float* p0 = g_gx + ((size_t)d * Mc + m) * 768 + g;
            float2 v0 = make_float2(acc[mi][ni][0] + bx, acc[mi][ni][1] + by);
            float2 v1 = make_float2(acc[mi][ni][2] + bx, acc[mi][ni][3] + by);
            *(float2*)p0 = v0;
            *(float2*)(p0 + 8 * 768) = v1;
        }
    }
}

// ---------- tensor-core GRU recurrence (fp16 2-term, mbarrier pipeline) ----------
constexpr int RROWS = 32;
constexpr int RTHREADS = 512;
constexpr int APITCH = 264;                 // fp16 elems per h-smem row
constexpr int NSTAGE = 3;
constexpr int HSM_E = RROWS * APITCH;       // h elems (single fp16)
constexpr int MBAR_OFF = NSTAGE * WCHUNK_B + HSM_E * 2;        // byte offset of mbars
constexpr int RECUR_SMEM = MBAR_OFF + 64;                      // 164416 B

__global__ void __launch_bounds__(RTHREADS, 1) gru_recur_mma(
    const float* __restrict__ bhh_all, int layer)
{
    extern __shared__ __half rsm[];
    const int tid = threadIdx.x;
    const int w = tid >> 5, lane = tid & 31;
    const int dir = blockIdx.y;
    const int b0 = blockIdx.x * RROWS;
    const int l2 = layer * 2 + dir;
    const float* bhh = bhh_all + (size_t)l2 * 768;
    const float* gxd = g_gx + (size_t)dir * Mc * 768;
    const __half* wsrc = g_whh + (size_t)l2 * 16 * WCHUNK_E;

    __half* hsm = rsm + NSTAGE * WCHUNK_E;
    const u32 smb = smem_u32(rsm);
    const u32 hsmb = smem_u32(hsm);
    const u32 mb_full  = smb + (u32)MBAR_OFF;        // 3 x 8B
    const u32 mb_empty = mb_full + 24;               // 3 x 8B

    for (int i = tid; i < HSM_E; i += RTHREADS)
        hsm[i] = __ushort_as_half(0);
    if (tid == 0) {
#pragma unroll
        for (int s = 0; s < NSTAGE; s++) {
            mbar_init(mb_full + s * 8, 1);
            mbar_init(mb_empty + s * 8, 16);
        }
    }
    __syncthreads();
    // pre-charge: every warp marks all stages empty (completes empty phase 0)
    if (lane == 0) {
#pragma unroll
        for (int s = 0; s < NSTAGE; s++) mbar_arrive(mb_empty + s * 8);
    }
    __syncthreads();

    constexpr int NCHUNK = Tc * 16;          // 208 chunk iterations per layer
    auto issue = [&](int cc_) {
        if (cc_ < NCHUNK) {
            const int s2 = cc_ % NSTAGE;
            mbar_wait(mb_empty + s2 * 8, (u32)((cc_ / NSTAGE) & 1));
            mbar_expect(mb_full + s2 * 8, WCHUNK_B);
            bulk_g2s(smb + (u32)s2 * WCHUNK_B, wsrc + (size_t)(cc_ & 15) * WCHUNK_E,
                     WCHUNK_B, mb_full + s2 * 8);
        }
    };
    if (tid == 0) { issue(0); issue(1); }

    const int c2 = (lane & 3) << 1;   // col pair base within n8
    const int r1 = lane >> 2;         // row within m8 group
    const int lr = lane & 15, lh = lane >> 4;
    const u32 swz = (u32)(((lr >> 2) & 1) << 4);   // B ldsm de-swizzle

    // precomputed ldsm base addresses
    u32 aoBase[2], bOff[3];
#pragma unroll
    for (int mt = 0; mt < 2; mt++)
        aoBase[mt] = (u32)(((mt * 16 + lr) * APITCH + lh * 8) * 2);
#pragma unroll
    for (int g = 0; g < 3; g++)
        bOff[g] = (u32)((g * 256 + w * 16 + lr) * 32) + (((u32)(lh << 4)) ^ swz);

    // recurrent biases for this thread's columns (per gate, per n8 sub-tile)
    float2 bh[3][2];
#pragma unroll
    for (int g = 0; g < 3; g++)
#pragma unroll
        for (int sub = 0; sub < 2; sub++)
            bh[g][sub] = *(const float2*)&bhh[g * 256 + w * 16 + sub * 8 + c2];

    // h (fp32) in C-fragment layout registers across steps
    float hprev[2][2][4];
#pragma unroll
    for (int mt = 0; mt < 2; mt++)
#pragma unroll
        for (int sub = 0; sub < 2; sub++)
#pragma unroll
            for (int e = 0; e < 4; e++) hprev[mt][sub][e] = 0.f;

    int c = 0;   // global chunk counter across steps

#pragma unroll 1
    for (int step = 0; step < Tc; step++) {
        const int tg = dir ? (Tc - 1 - step) : step;

        float acc[2][6][4];
#pragma unroll
        for (int mt = 0; mt < 2; mt++)
#pragma unroll
            for (int t = 0; t < 6; t++)
#pragma unroll
                for (int e = 0; e < 4; e++) acc[mt][t][e] = 0.f;

#pragma unroll 1
        for (int kc = 0; kc < 16; kc++) {
            if (tid == 0) issue(c + 2);
            const int s = c % NSTAGE;
            mbar_wait(mb_full + s * 8, (u32)((c / NSTAGE) & 1));

            // A fragments from h smem (single fp16), 2 m16 tiles
            const u32 akk = (u32)(kc * 32);
            u32 ah[2][4];
#pragma unroll
            for (int mt = 0; mt < 2; mt++)
                ldsm_x4(ah[mt][0], ah[mt][1], ah[mt][2], ah[mt][3], hsmb + aoBase[mt] + akk);

            const u32 sbase = smb + (u32)s * WCHUNK_B;
            u32 bhr[3][2][2], blr[3][2][2];
#pragma unroll
            for (int g = 0; g < 3; g++) {
                const u32 ad = sbase + bOff[g];
                u32 t0, t1, t2, t3;
                ldsm_x4(t0, t1, t2, t3, ad);
                bhr[g][0][0] = t0; bhr[g][1][0] = t1; bhr[g][0][1] = t2; bhr[g][1][1] = t3;
                ldsm_x4(t0, t1, t2, t3, ad + 24576);   // lo half of chunk
                blr[g][0][0] = t0; blr[g][1][0] = t1; blr[g][0][1] = t2; blr[g][1][1] = t3;
            }
            if (lane == 0) mbar_arrive(mb_empty + s * 8);   // warp done with stage s

#pragma unroll
            for (int g = 0; g < 3; g++)
#pragma unroll
                for (int mt = 0; mt < 2; mt++)
#pragma unroll
                    for (int nt = 0; nt < 2; nt++) {
                        float* d = acc[mt][g * 2 + nt];
                        mma_f16(d, ah[mt], bhr[g][nt]);
                        mma_f16(d, ah[mt], blr[g][nt]);
                    }
            c++;
        }

        // gate math entirely in registers
#pragma unroll
        for (int mt = 0; mt < 2; mt++)
#pragma unroll
            for (int sub = 0; sub < 2; sub++) {
                const int jc = w * 16 + sub * 8 + c2;
                const float2 br = bh[0][sub], bz = bh[1][sub], bn = bh[2][sub];
#pragma unroll
                for (int half = 0; half < 2; half++) {
                    const int row = mt * 16 + r1 + half * 8;
                    const int b = b0 + row;
                    const float* gxrow = gxd + ((size_t)b * Tc + tg) * 768 + jc;
                    const float2 xr = *(const float2*)gxrow;
                    const float2 xz = *(const float2*)(gxrow + 256);
                    const float2 xn = *(const float2*)(gxrow + 512);
                    const int e = half * 2;
                    float rx = sigf(xr.x + acc[mt][sub][e]     + br.x);
                    float ry = sigf(xr.y + acc[mt][sub][e + 1] + br.y);
                    float zx = sigf(xz.x + acc[mt][2 + sub][e]     + bz.x);
                    float zy = sigf(xz.y + acc[mt][2 + sub][e + 1] + bz.y);
                    float nx = tanhfast(xn.x + rx * (acc[mt][4 + sub][e]     + bn.x));
                    float ny = tanhfast(xn.y + ry * (acc[mt][4 + sub][e + 1] + bn.y));
                    float hx = (1.f - zx) * nx + zx * hprev[mt][sub][e];
                    float hy = (1.f - zy) * ny + zy * hprev[mt][sub][e + 1];
                    hprev[mt][sub][e] = hx;
                    hprev[mt][sub][e + 1] = hy;
                }
            }

        __syncthreads();   // all warps done reading h smem this step

        // write new h (single fp16): smem (A layout) + g_a (+ hsum)
#pragma unroll
        for (int mt = 0; mt < 2; mt++)
#pragma unroll
            for (int sub = 0; sub < 2; sub++) {
                const int jc = w * 16 + sub * 8 + c2;
#pragma unroll
                for (int half = 0; half < 2; half++) {
                    const int row = mt * 16 + r1 + half * 8;
                    const int b = b0 + row;
                    const int e = half * 2;
                    const float hx = hprev[mt][sub][e];
                    const float hy = hprev[mt][sub][e + 1];
                    const u32 ph = cvt2h(hx, hy);
                    *(u32*)(hsm + row * APITCH + jc) = ph;
                    const size_t ob = ((size_t)b * Tc + tg) * 512 + dir * 256 + jc;
                    *(u32*)(g_a + ob) = ph;
                    if (step == Tc - 1) {
                        float* hp = g_hsum + ((size_t)dir * Bc + b) * 256 + jc;
                        float2 cur = *(const float2*)hp;
                        cur.x += hx; cur.y += hy;
                        *(float2*)hp = cur;
                    }
                }
            }
        __syncthreads();   // h writes visible before next step's A ldsm
    }
}

// ---------- head: mean over 16 finals -> silu MLP -> scalar ----------
__global__ void head_kernel(const float* __restrict__ W1, const float* __restrict__ b1,
                            const float* __restrict__ W2, const float* __restrict__ b2,
                            const float* __restrict__ Wc, const float* __restrict__ bc,
                            float* __restrict__ out)
{
    const int b = blockIdx.x;
    const int tid = threadIdx.x;   // 64 threads
    __shared__ float hs[256];
    __shared__ float s1[64];
    for (int i = tid; i < 256; i += 64)
        hs[i] = (g_hsum[(size_t)b * 256 + i] + g_hsum[(size_t)(Bc + b) * 256 + i]) * (1.f / 16.f);
    __syncthreads();
    float a1 = b1[tid];
    const float* w1r = W1 + (size_t)tid * 256;
#pragma unroll 4
    for (int k = 0; k < 256; k++) a1 += hs[k] * w1r[k];
    s1[tid] = a1 * sigmf(a1);
    __syncthreads();
    if (tid < 32) {
        float a2 = b2[tid];
        const float* w2r = W2 + (size_t)tid * 64;
#pragma unroll
        for (int k = 0; k < 64; k++) a2 += s1[k] * w2r[k];
        float y = a2 * sigmf(a2);
        float v = y * Wc[tid];
#pragma unroll
        for (int o = 16; o > 0; o >>= 1) v += __shfl_down_sync(0xffffffffu, v, o);
        if (tid == 0) out[b] = v + bc[0];
    }
}

// ---------- launch ----------
extern "C" void kernel_launch(void* const* d_in, const int* in_sizes, int n_in,
                              void* d_out, int out_size) {
    (void)in_sizes; (void)n_in; (void)out_size;
    const float* x         = (const float*)d_in[0];
    const float* W_ih0     = (const float*)d_in[1];
    const float* W_ih_rest = (const float*)d_in[2];
    const float* W_hh      = (const float*)d_in[3];
    const float* b_ih      = (const float*)d_in[4];
    const float* b_hh      = (const float*)d_in[5];
    const float* W1        = (const float*)d_in[6];
    const float* b1        = (const float*)d_in[7];
    const float* W2        = (const float*)d_in[8];
    const float* b2        = (const float*)d_in[9];
    const float* Wc        = (const float*)d_in[10];
    const float* bc        = (const float*)d_in[11];
    float* out = (float*)d_out;

    cudaFuncSetAttribute(gemm_gx_mma,
                         cudaFuncAttributeMaxDynamicSharedMemorySize, GEMM_SMEM);
    cudaFuncSetAttribute(gru_recur_mma,
                         cudaFuncAttributeMaxDynamicSharedMemorySize, RECUR_SMEM);

    // 4 prep launches so ncu (-s 5 -c 1) captures launch index 5 = gru_recur_mma l0.
    const size_t NPREP1 = (size_t)Mc * K0P + WIH_ELEMS;
    convert_inputs_kernel<<<(int)((NPREP1 + 255) / 256), 256>>>(x, W_ih0, W_ih_rest);
    convert_whh_kernel<<<(int)((WHH_ELEMS + 255) / 256), 256>>>(W_hh);
    zero_hsum_a<<<(Bc * Hc + 255) / 256, 256>>>();
    zero_hsum_b<<<(Bc * Hc + 255) / 256, 256>>>();

    dim3 ggrid(12, 208);            // N/128, M/128
    dim3 rgrid(Bc / RROWS, 2);      // 64 x 2 dirs

    for (int l = 0; l < 8; l++) {
        gemm_gx_mma<<<ggrid, 256, GEMM_SMEM>>>(l, b_ih + (size_t)l * 1536);
        gru_recur_mma<<<rgrid, RTHREADS, RECUR_SMEM>>>(b_hh, l);
    }

    head_kernel<<<Bc, 64>>>(W1, b1, W2, b2, Wc, bc, out);
}

// round 16
// speedup vs baseline: 1.5818x; 1.1186x over previous
#include <cuda_runtime.h>
#include <cuda_fp16.h>
#include <cstdint>
#include <cstddef>
#include <math.h>

typedef unsigned long long ull;
typedef unsigned int u32;
typedef unsigned short u16;

// Problem constants
constexpr int Bc = 2048;
constexpr int Tc = 13;
constexpr int Hc = 256;
constexpr int Mc = Bc * Tc;      // 26624 rows for the input GEMMs
constexpr int K0P = 192;         // layer-0 K (188) padded to multiple of 16

// Scratch (device globals: allocation-free rule)
__device__ __half g_gx[(size_t)2 * Mc * 768];   // [dir][b*T+t][768] fp16 gate pre-acts
__device__ float g_hsum[(size_t)2 * Bc * Hc];   // [dir][b][256] summed over layers

// fp16 operands: activations single fp16 (incoherent rounding), input-GEMM
// weights split hi+lo fp16 (error 2^-22), recurrent weights single fp16.
__device__ __half g_x[(size_t)Mc * K0P];
constexpr size_t WIH_ELEMS = (size_t)1536 * K0P + (size_t)7 * 1536 * 512;
__device__ __half g_w_hi[WIH_ELEMS];
__device__ __half g_w_lo[WIH_ELEMS];
__device__ __half g_a[(size_t)Mc * 512];        // layer outputs (next-layer A)

// W_hh single fp16, packed per (l2, kchunk): [768 rows x 16 k] XOR-swizzled.
// One chunk = 24576 bytes contiguous (single cp.async.bulk).
constexpr int WCHUNK_E = 12288;              // elements per chunk
constexpr int WCHUNK_B = WCHUNK_E * 2;       // 24576 bytes
__device__ __align__(128) __half g_whh[(size_t)16 * 16 * WCHUNK_E];

// ---------- math helpers ----------
__device__ __forceinline__ float sigmf(float x) { return 1.f / (1.f + expf(-x)); }
__device__ __forceinline__ float sigf(float x)  { return __fdividef(1.f, 1.f + __expf(-x)); }
__device__ __forceinline__ float tanhfast(float x) { return 2.f * sigf(2.f * x) - 1.f; }

__device__ __forceinline__ void split_h16(float v, u16& h, u16& l) {
    __half hh = __float2half_rn(v);
    float r = v - __half2float(hh);
    h = __half_as_ushort(hh);
    l = __half_as_ushort(__float2half_rn(r));
}

// pack two fp32 -> f16x2 in one value (x = low half)
__device__ __forceinline__ u32 cvt2h(float x, float y) {
    __half2 p = __floats2half2_rn(x, y);
    return *reinterpret_cast<u32*>(&p);
}
__device__ __forceinline__ float2 h2f2(u32 v) {
    __half2 p = *reinterpret_cast<__half2*>(&v);
    return __half22float2(p);
}

// ---------- mma / smem helpers ----------
__device__ __forceinline__ u32 smem_u32(const void* p) {
    return (u32)__cvta_generic_to_shared(p);
}
__device__ __forceinline__ void ldsm_x4(u32& r0, u32& r1, u32& r2, u32& r3, u32 addr) {
    asm volatile("ldmatrix.sync.aligned.m8n8.x4.shared.b16 {%0,%1,%2,%3}, [%4];\n"
                 : "=r"(r0), "=r"(r1), "=r"(r2), "=r"(r3) : "r"(addr));
}
__device__ __forceinline__ void mma_f16(float* d, const u32* a, const u32* b) {
    asm volatile("mma.sync.aligned.m16n8k16.row.col.f32.f16.f16.f32 "
                 "{%0,%1,%2,%3}, {%4,%5,%6,%7}, {%8,%9}, {%0,%1,%2,%3};\n"
                 : "+f"(d[0]), "+f"(d[1]), "+f"(d[2]), "+f"(d[3])
                 : "r"(a[0]), "r"(a[1]), "r"(a[2]), "r"(a[3]), "r"(b[0]), "r"(b[1]));
}
__device__ __forceinline__ void cp16(u32 dst, const void* src) {
    asm volatile("cp.async.cg.shared.global [%0], [%1], 16;" :: "r"(dst), "l"(src));
}
#define CP_COMMIT() asm volatile("cp.async.commit_group;\n" ::: "memory")
#define CP_WAIT2()  asm volatile("cp.async.wait_group 2;\n" ::: "memory")

// ---------- mbarrier + bulk-copy helpers ----------
__device__ __forceinline__ void mbar_init(u32 mbar, u32 cnt) {
    asm volatile("mbarrier.init.shared.b64 [%0], %1;" :: "r"(mbar), "r"(cnt) : "memory");
}
__device__ __forceinline__ void mbar_expect(u32 mbar, u32 bytes) {
    asm volatile("mbarrier.arrive.expect_tx.shared.b64 _, [%0], %1;"
                 :: "r"(mbar), "r"(bytes) : "memory");
}
__device__ __forceinline__ void mbar_arrive(u32 mbar) {
    asm volatile("mbarrier.arrive.shared.b64 _, [%0];" :: "r"(mbar) : "memory");
}
__device__ __forceinline__ void bulk_g2s(u32 dst, const void* src, u32 bytes, u32 mbar) {
    asm volatile("cp.async.bulk.shared::cta.global.mbarrier::complete_tx::bytes "
                 "[%0], [%1], %2, [%3];"
                 :: "r"(dst), "l"(src), "r"(bytes), "r"(mbar) : "memory");
}
__device__ __forceinline__ void mbar_wait(u32 mbar, u32 parity) {
    asm volatile(
        "{\n\t"
        ".reg .pred P;\n\t"
        "WL%=:\n\t"
        "mbarrier.try_wait.parity.acquire.cta.shared::cta.b64 P, [%0], %1, 0x989680;\n\t"
        "@P bra WD%=;\n\t"
        "bra WL%=;\n\t"
        "WD%=:\n\t"
        "}"
        :: "r"(mbar), "r"(parity) : "memory");
}

// ---------- prep kernel 1: convert x (single fp16) + W_ih (split fp16) ----------
__global__ void convert_inputs_kernel(const float* __restrict__ x,
                                      const float* __restrict__ W0,
                                      const float* __restrict__ Wr) {
    size_t i = (size_t)blockIdx.x * blockDim.x + threadIdx.x;
    const size_t NX = (size_t)Mc * K0P;
    if (i < NX) {
        int row = (int)(i / K0P), col = (int)(i - (size_t)row * K0P);
        float v = (col < 188) ? x[(size_t)row * 188 + col] : 0.f;
        g_x[i] = __float2half_rn(v);
    } else if (i < NX + WIH_ELEMS) {
        size_t j = i - NX;
        float v;
        if (j < (size_t)1536 * K0P) {
            int row = (int)(j / K0P), col = (int)(j - (size_t)row * K0P);
            v = (col < 188) ? W0[(size_t)row * 188 + col] : 0.f;
        } else {
            v = Wr[j - (size_t)1536 * K0P];
        }
        u16 h, l;
        split_h16(v, h, l);
        g_w_hi[j] = __ushort_as_half(h);
        g_w_lo[j] = __ushort_as_half(l);
    }
}

// ---------- prep kernel 2: convert W_hh (swizzled single-fp16 chunks) + zero hsum ----------
constexpr size_t WHH_ELEMS = (size_t)16 * 768 * 256;
__global__ void convert_whh_zero_kernel(const float* __restrict__ Whh) {
    size_t i = (size_t)blockIdx.x * blockDim.x + threadIdx.x;
    if (i < (size_t)2 * Bc * Hc) g_hsum[i] = 0.f;
    if (i >= WHH_ELEMS) return;
    size_t l2 = i / ((size_t)768 * 256);
    size_t rem = i - l2 * 768 * 256;
    int n = (int)(rem / 256), k = (int)(rem % 256);
    float v = Whh[i];
    int kk = k & 15;
    // XOR swizzle: 16B-half index ^= (n>>2)&1  -> conflict-free ldmatrix phases
    u32 swb = (((u32)(kk >> 3) ^ (u32)((n >> 2) & 1)) << 4);
    size_t byte_in = (size_t)n * 32 + swb + (size_t)(kk & 7) * 2;
    size_t o = ((size_t)l2 * 16 + (size_t)(k >> 4)) * WCHUNK_E + byte_in / 2;
    g_whh[o] = __float2half_rn(v);
}

// ---------- input GEMM (tensor cores, fp16 2-term W, cp.async 4-stage) ----------
constexpr int GPITCH = 24;                  // fp16 elems per smem row (48B)
constexpr int GTSZ = 128 * GPITCH;          // elems per (stage,op) tile
constexpr int GSTAGES = 4;
constexpr int GEMM_SMEM = GSTAGES * 3 * GTSZ * 2; // 73728 B

__global__ void __launch_bounds__(256, 2) gemm_gx_mma(int layer, const float* __restrict__ bias) {
    extern __shared__ __half sm[];

    const __half *A, *Whi, *Wlo;
    int K;
    if (layer == 0) {
        A = g_x; Whi = g_w_hi; Wlo = g_w_lo; K = K0P;
    } else {
        size_t wo = (size_t)1536 * K0P + (size_t)(layer - 1) * 1536 * 512;
        A = g_a; Whi = g_w_hi + wo; Wlo = g_w_lo + wo; K = 512;
    }

    const int tid = threadIdx.x;
    const int m0 = blockIdx.y * 128;
    const int n0 = blockIdx.x * 128;

    const int lrow = tid >> 1;
    const int lhalf = tid & 1;
    const size_t aoff = (size_t)(m0 + lrow) * K + lhalf * 8;
    const size_t boff = (size_t)(n0 + lrow) * K + lhalf * 8;
    const u32 smoffB = (u32)(lrow * GPITCH + lhalf * 8) * 2;   // bytes

    const int wid = tid >> 5, lane = tid & 31;
    const int wm = (wid & 1) << 6;
    const int wn = (wid >> 1) << 5;

    float acc[4][4][4];
#pragma unroll
    for (int mi = 0; mi < 4; mi++)
#pragma unroll
        for (int ni = 0; ni < 4; ni++)
#pragma unroll
            for (int e = 0; e < 4; e++) acc[mi][ni][e] = 0.f;

    const int lr = lane & 15, lh = lane >> 4;
    int aoffs[4], boffs[2];
#pragma unroll
    for (int mi = 0; mi < 4; mi++)
        aoffs[mi] = ((wm + mi * 16 + lr) * GPITCH + lh * 8) * 2;
#pragma unroll
    for (int p = 0; p < 2; p++)
        boffs[p] = ((wn + p * 16 + lr) * GPITCH + lh * 8) * 2;

    const u32 smb = smem_u32(sm);
    const int nk = K >> 4;
    constexpr u32 STB = 3 * GTSZ * 2;       // bytes per stage (A, Whi, Wlo)

    auto load_chunk = [&](int kc, int s) {
        const size_t ka = (size_t)kc * 16;
        const u32 d = smb + (u32)s * STB + smoffB;
        cp16(d + 0 * GTSZ * 2, A   + aoff + ka);
        cp16(d + 1 * GTSZ * 2, Whi + boff + ka);
        cp16(d + 2 * GTSZ * 2, Wlo + boff + ka);
    };

    // prologue: 3 chunks in flight
#pragma unroll
    for (int s = 0; s < GSTAGES - 1; s++) { load_chunk(s, s); CP_COMMIT(); }

#pragma unroll 1
    for (int kc = 0; kc < nk; kc++) {
        CP_WAIT2();                          // oldest (stage kc) complete; 2 in flight
        __syncthreads();                     // all warps done reading recycled stage
        if (kc + GSTAGES - 1 < nk) { load_chunk(kc + GSTAGES - 1, (kc + GSTAGES - 1) & 3); CP_COMMIT(); }

        const u32 sbase = smb + (u32)(kc & 3) * STB;
        u32 a[4][4], bhi[4][2], blo[4][2];
#pragma unroll
        for (int mi = 0; mi < 4; mi++)
            ldsm_x4(a[mi][0], a[mi][1], a[mi][2], a[mi][3], sbase + aoffs[mi]);
#pragma unroll
        for (int p = 0; p < 2; p++) {
            u32 t0, t1, t2, t3;
            ldsm_x4(t0, t1, t2, t3, sbase + boffs[p] + 1 * GTSZ * 2);
            bhi[2 * p][0] = t0; bhi[2 * p + 1][0] = t1;
            bhi[2 * p][1] = t2; bhi[2 * p + 1][1] = t3;
            ldsm_x4(t0, t1, t2, t3, sbase + boffs[p] + 2 * GTSZ * 2);
            blo[2 * p][0] = t0; blo[2 * p + 1][0] = t1;
            blo[2 * p][1] = t2; blo[2 * p + 1][1] = t3;
        }

#pragma unroll
        for (int mi = 0; mi < 4; mi++)
#pragma unroll
            for (int ni = 0; ni < 4; ni++) {
                mma_f16(acc[mi][ni], a[mi], bhi[ni]);
                mma_f16(acc[mi][ni], a[mi], blo[ni]);
            }
    }

    // epilogue: add bias, pack to fp16, scatter to gx[dir][m][g]
    const int cr = lane >> 2;
    const int cc = (lane & 3) << 1;
#pragma unroll
    for (int ni = 0; ni < 4; ni++) {
        const int n = n0 + wn + ni * 8 + cc;
        const int d = (n >= 768) ? 1 : 0;
        const int g = n - d * 768;
        const float bx = bias[n], by = bias[n + 1];
#pragma unroll
        for (int mi = 0; mi < 4; mi++) {
            const int m = m0 + wm + mi * 16 + cr;
            __half* p0 = g_gx + ((size_t)d * Mc + m) * 768 + g;
            *(u32*)p0 = cvt2h(acc[mi][ni][0] + bx, acc[mi][ni][1] + by);
            *(u32*)(p0 + 8 * 768) = cvt2h(acc[mi][ni][2] + bx, acc[mi][ni][3] + by);
        }
    }
}

// ---------- tensor-core GRU recurrence (single-fp16 W, mbarrier pipeline) ----------
constexpr int RROWS = 32;
constexpr int RTHREADS = 512;
constexpr int APITCH = 264;                 // fp16 elems per h-smem row
constexpr int NSTAGE = 4;
constexpr int HSM_E = RROWS * APITCH;       // h elems (single fp16)
constexpr int MBAR_OFF = NSTAGE * WCHUNK_B + HSM_E * 2;        // byte offset of mbars
constexpr int RECUR_SMEM = MBAR_OFF + 80;                      // ~115 KB

__global__ void __launch_bounds__(RTHREADS, 1) gru_recur_mma(
    const float* __restrict__ bhh_all, int layer)
{
    extern __shared__ __half rsm[];
    const int tid = threadIdx.x;
    const int w = tid >> 5, lane = tid & 31;
    const int dir = blockIdx.y;
    const int b0 = blockIdx.x * RROWS;
    const int l2 = layer * 2 + dir;
    const float* bhh = bhh_all + (size_t)l2 * 768;
    const __half* gxd = g_gx + (size_t)dir * Mc * 768;
    const __half* wsrc = g_whh + (size_t)l2 * 16 * WCHUNK_E;

    __half* hsm = rsm + NSTAGE * WCHUNK_E;
    const u32 smb = smem_u32(rsm);
    const u32 hsmb = smem_u32(hsm);
    const u32 mb_full  = smb + (u32)MBAR_OFF;        // 4 x 8B
    const u32 mb_empty = mb_full + NSTAGE * 8;       // 4 x 8B

    for (int i = tid; i < HSM_E; i += RTHREADS)
        hsm[i] = __ushort_as_half(0);
    if (tid == 0) {
#pragma unroll
        for (int s = 0; s < NSTAGE; s++) {
            mbar_init(mb_full + s * 8, 1);
            mbar_init(mb_empty + s * 8, 16);
        }
    }
    __syncthreads();
    // pre-charge: every warp marks all stages empty (completes empty phase 0)
    if (lane == 0) {
#pragma unroll
        for (int s = 0; s < NSTAGE; s++) mbar_arrive(mb_empty + s * 8);
    }
    __syncthreads();

    constexpr int NCHUNK = Tc * 16;          // 208 chunk iterations per layer
    auto issue = [&](int cc_) {
        if (cc_ < NCHUNK) {
            const int s2 = cc_ % NSTAGE;
            mbar_wait(mb_empty + s2 * 8, (u32)((cc_ / NSTAGE) & 1));
            mbar_expect(mb_full + s2 * 8, WCHUNK_B);
            bulk_g2s(smb + (u32)s2 * WCHUNK_B, wsrc + (size_t)(cc_ & 15) * WCHUNK_E,
                     WCHUNK_B, mb_full + s2 * 8);
        }
    };
    if (tid == 0) { issue(0); issue(1); issue(2); }

    const int c2 = (lane & 3) << 1;   // col pair base within n8
    const int r1 = lane >> 2;         // row within m8 group
    const int lr = lane & 15, lh = lane >> 4;
    const u32 swz = (u32)(((lr >> 2) & 1) << 4);   // B ldsm de-swizzle

    // precomputed ldsm base addresses
    u32 aoBase[2], bOff[3];
#pragma unroll
    for (int mt = 0; mt < 2; mt++)
        aoBase[mt] = (u32)(((mt * 16 + lr) * APITCH + lh * 8) * 2);
#pragma unroll
    for (int g = 0; g < 3; g++)
        bOff[g] = (u32)((g * 256 + w * 16 + lr) * 32) + (((u32)(lh << 4)) ^ swz);

    // recurrent biases for this thread's columns (per gate, per n8 sub-tile)
    float2 bh[3][2];
#pragma unroll
    for (int g = 0; g < 3; g++)
#pragma unroll
        for (int sub = 0; sub < 2; sub++)
            bh[g][sub] = *(const float2*)&bhh[g * 256 + w * 16 + sub * 8 + c2];

    // h (fp32) in C-fragment layout registers across steps
    float hprev[2][2][4];
#pragma unroll
    for (int mt = 0; mt < 2; mt++)
#pragma unroll
        for (int sub = 0; sub < 2; sub++)
#pragma unroll
            for (int e = 0; e < 4; e++) hprev[mt][sub][e] = 0.f;

    int c = 0;   // global chunk counter across steps

#pragma unroll 1
    for (int step = 0; step < Tc; step++) {
        const int tg = dir ? (Tc - 1 - step) : step;

        float acc[2][6][4];
#pragma unroll
        for (int mt = 0; mt < 2; mt++)
#pragma unroll
            for (int t = 0; t < 6; t++)
#pragma unroll
                for (int e = 0; e < 4; e++) acc[mt][t][e] = 0.f;

#pragma unroll 1
        for (int kc = 0; kc < 16; kc++) {
            if (tid == 0) issue(c + 3);
            const int s = c % NSTAGE;
            mbar_wait(mb_full + s * 8, (u32)((c / NSTAGE) & 1));

            // A fragments from h smem (single fp16), 2 m16 tiles
            const u32 akk = (u32)(kc * 32);
            u32 ah[2][4];
#pragma unroll
            for (int mt = 0; mt < 2; mt++)
                ldsm_x4(ah[mt][0], ah[mt][1], ah[mt][2], ah[mt][3], hsmb + aoBase[mt] + akk);

            const u32 sbase = smb + (u32)s * WCHUNK_B;
            u32 bfr[3][2][2];
#pragma unroll
            for (int g = 0; g < 3; g++) {
                u32 t0, t1, t2, t3;
                ldsm_x4(t0, t1, t2, t3, sbase + bOff[g]);
                bfr[g][0][0] = t0; bfr[g][1][0] = t1; bfr[g][0][1] = t2; bfr[g][1][1] = t3;
            }
            if (lane == 0) mbar_arrive(mb_empty + s * 8);   // warp done with stage s

#pragma unroll
            for (int g = 0; g < 3; g++)
#pragma unroll
                for (int mt = 0; mt < 2; mt++)
#pragma unroll
                    for (int nt = 0; nt < 2; nt++)
                        mma_f16(acc[mt][g * 2 + nt], ah[mt], bfr[g][nt]);
            c++;
        }

        // gate math entirely in registers (gx loaded as fp16 pairs)
#pragma unroll
        for (int mt = 0; mt < 2; mt++)
#pragma unroll
            for (int sub = 0; sub < 2; sub++) {
                const int jc = w * 16 + sub * 8 + c2;
                const float2 br = bh[0][sub], bz = bh[1][sub], bn = bh[2][sub];
#pragma unroll
                for (int half = 0; half < 2; half++) {
                    const int row = mt * 16 + r1 + half * 8;
                    const int b = b0 + row;
                    const __half* gxrow = gxd + ((size_t)b * Tc + tg) * 768 + jc;
                    const float2 xr = h2f2(*(const u32*)gxrow);
                    const float2 xz = h2f2(*(const u32*)(gxrow + 256));
                    const float2 xn = h2f2(*(const u32*)(gxrow + 512));
                    const int e = half * 2;
                    float rx = sigf(xr.x + acc[mt][sub][e]     + br.x);
                    float ry = sigf(xr.y + acc[mt][sub][e + 1] + br.y);
                    float zx = sigf(xz.x + acc[mt][2 + sub][e]     + bz.x);
                    float zy = sigf(xz.y + acc[mt][2 + sub][e + 1] + bz.y);
                    float nx = tanhfast(xn.x + rx * (acc[mt][4 + sub][e]     + bn.x));
                    float ny = tanhfast(xn.y + ry * (acc[mt][4 + sub][e + 1] + bn.y));
                    float hx = (1.f - zx) * nx + zx * hprev[mt][sub][e];
                    float hy = (1.f - zy) * ny + zy * hprev[mt][sub][e + 1];
                    hprev[mt][sub][e] = hx;
                    hprev[mt][sub][e + 1] = hy;
                }
            }

        __syncthreads();   // all warps done reading h smem this step

        // write new h (single fp16): smem (A layout) + g_a (+ hsum)
#pragma unroll
        for (int mt = 0; mt < 2; mt++)
#pragma unroll
            for (int sub = 0; sub < 2; sub++) {
                const int jc = w * 16 + sub * 8 + c2;
#pragma unroll
                for (int half = 0; half < 2; half++) {
                    const int row = mt * 16 + r1 + half * 8;
                    const int b = b0 + row;
                    const int e = half * 2;
                    const float hx = hprev[mt][sub][e];
                    const float hy = hprev[mt][sub][e + 1];
                    const u32 ph = cvt2h(hx, hy);
                    *(u32*)(hsm + row * APITCH + jc) = ph;
                    const size_t ob = ((size_t)b * Tc + tg) * 512 + dir * 256 + jc;
                    *(u32*)(g_a + ob) = ph;
                    if (step == Tc - 1) {
                        float* hp = g_hsum + ((size_t)dir * Bc + b) * 256 + jc;
                        float2 cur = *(const float2*)hp;
                        cur.x += hx; cur.y += hy;
                        *(float2*)hp = cur;
                    }
                }
            }
        __syncthreads();   // h writes visible before next step's A ldsm
    }
}

// ---------- head: mean over 16 finals -> silu MLP -> scalar ----------
__global__ void head_kernel(const float* __restrict__ W1, const float* __restrict__ b1,
                            const float* __restrict__ W2, const float* __restrict__ b2,
                            const float* __restrict__ Wc, const float* __restrict__ bc,
                            float* __restrict__ out)
{
    const int b = blockIdx.x;
    const int tid = threadIdx.x;   // 64 threads
    __shared__ float hs[256];
    __shared__ float s1[64];
    for (int i = tid; i < 256; i += 64)
        hs[i] = (g_hsum[(size_t)b * 256 + i] + g_hsum[(size_t)(Bc + b) * 256 + i]) * (1.f / 16.f);
    __syncthreads();
    float a1 = b1[tid];
    const float* w1r = W1 + (size_t)tid * 256;
#pragma unroll 4
    for (int k = 0; k < 256; k++) a1 += hs[k] * w1r[k];
    s1[tid] = a1 * sigmf(a1);
    __syncthreads();
    if (tid < 32) {
        float a2 = b2[tid];
        const float* w2r = W2 + (size_t)tid * 64;
#pragma unroll
        for (int k = 0; k < 64; k++) a2 += s1[k] * w2r[k];
        float y = a2 * sigmf(a2);
        float v = y * Wc[tid];
#pragma unroll
        for (int o = 16; o > 0; o >>= 1) v += __shfl_down_sync(0xffffffffu, v, o);
        if (tid == 0) out[b] = v + bc[0];
    }
}

// ---------- launch ----------
extern "C" void kernel_launch(void* const* d_in, const int* in_sizes, int n_in,
                              void* d_out, int out_size) {
    (void)in_sizes; (void)n_in; (void)out_size;
    const float* x         = (const float*)d_in[0];
    const float* W_ih0     = (const float*)d_in[1];
    const float* W_ih_rest = (const float*)d_in[2];
    const float* W_hh      = (const float*)d_in[3];
    const float* b_ih      = (const float*)d_in[4];
    const float* b_hh      = (const float*)d_in[5];
    const float* W1        = (const float*)d_in[6];
    const float* b1        = (const float*)d_in[7];
    const float* W2        = (const float*)d_in[8];
    const float* b2        = (const float*)d_in[9];
    const float* Wc        = (const float*)d_in[10];
    const float* bc        = (const float*)d_in[11];
    float* out = (float*)d_out;

    cudaFuncSetAttribute(gemm_gx_mma,
                         cudaFuncAttributeMaxDynamicSharedMemorySize, GEMM_SMEM);
    cudaFuncSetAttribute(gru_recur_mma,
                         cudaFuncAttributeMaxDynamicSharedMemorySize, RECUR_SMEM);

    // 2 prep launches -> ncu's captured launch (index 3) = gru_recur_mma layer 0.
    const size_t NPREP1 = (size_t)Mc * K0P + WIH_ELEMS;
    convert_inputs_kernel<<<(int)((NPREP1 + 255) / 256), 256>>>(x, W_ih0, W_ih_rest);
    convert_whh_zero_kernel<<<(int)((WHH_ELEMS + 255) / 256), 256>>>(W_hh);

    dim3 ggrid(12, 208);            // N/128, M/128
    dim3 rgrid(Bc / RROWS, 2);      // 64 x 2 dirs

    for (int l = 0; l < 8; l++) {
        gemm_gx_mma<<<ggrid, 256, GEMM_SMEM>>>(l, b_ih + (size_t)l * 1536);
        gru_recur_mma<<<rgrid, RTHREADS, RECUR_SMEM>>>(b_hh, l);
    }

    head_kernel<<<Bc, 64>>>(W1, b1, W2, b2, Wc, bc, out);
}

// round 17
// speedup vs baseline: 2.2640x; 1.4313x over previous
#include <cuda_runtime.h>
#include <cuda_fp16.h>
#include <cstdint>
#include <cstddef>
#include <math.h>

typedef unsigned long long ull;
typedef unsigned int u32;
typedef unsigned short u16;

// Problem constants
constexpr int Bc = 2048;
constexpr int Tc = 13;
constexpr int Hc = 256;
constexpr int Mc = Bc * Tc;      // 26624 rows for the input GEMMs
constexpr int K0P = 192;         // layer-0 K (188) padded to multiple of 16

// Scratch (device globals: allocation-free rule)
__device__ __half g_gx[(size_t)2 * Mc * 768];   // [dir][b*T+t][768] fp16 gate pre-acts
__device__ float g_hsum[(size_t)2 * Bc * Hc];   // [dir][b][256] summed over layers

// fp16 operands (all single precision; gx-storage rounding dominates the budget)
__device__ __half g_x[(size_t)Mc * K0P];
constexpr size_t WIH_ELEMS = (size_t)1536 * K0P + (size_t)7 * 1536 * 512;
__device__ __half g_w[WIH_ELEMS];
__device__ __half g_a[(size_t)Mc * 512];        // layer outputs (next-layer A)

// W_hh single fp16, packed per (l2, kchunk32): 768 rows x 64B, swizzled
// q' = q ^ ((n>>1)&3) so every ldmatrix phase hits 8 distinct 16B banks.
// One chunk = 49152 bytes contiguous (single cp.async.bulk).
constexpr int WCHUNK_E = 24576;              // elements per chunk (768 x 32 k)
constexpr int WCHUNK_B = WCHUNK_E * 2;       // 49152 bytes
__device__ __align__(128) __half g_whh[(size_t)16 * 8 * WCHUNK_E];

// ---------- math helpers ----------
__device__ __forceinline__ float sigmf(float x) { return 1.f / (1.f + expf(-x)); }
__device__ __forceinline__ float sigf(float x)  { return __fdividef(1.f, 1.f + __expf(-x)); }
__device__ __forceinline__ float tanhfast(float x) { return 2.f * sigf(2.f * x) - 1.f; }

// pack two fp32 -> f16x2 in one value (x = low half)
__device__ __forceinline__ u32 cvt2h(float x, float y) {
    __half2 p = __floats2half2_rn(x, y);
    return *reinterpret_cast<u32*>(&p);
}
__device__ __forceinline__ float2 h2f2(u32 v) {
    __half2 p = *reinterpret_cast<__half2*>(&v);
    return __half22float2(p);
}

// ---------- mma / smem helpers ----------
__device__ __forceinline__ u32 smem_u32(const void* p) {
    return (u32)__cvta_generic_to_shared(p);
}
__device__ __forceinline__ void ldsm_x4(u32& r0, u32& r1, u32& r2, u32& r3, u32 addr) {
    asm volatile("ldmatrix.sync.aligned.m8n8.x4.shared.b16 {%0,%1,%2,%3}, [%4];\n"
                 : "=r"(r0), "=r"(r1), "=r"(r2), "=r"(r3) : "r"(addr));
}
__device__ __forceinline__ void mma_f16(float* d, const u32* a, const u32* b) {
    asm volatile("mma.sync.aligned.m16n8k16.row.col.f32.f16.f16.f32 "
                 "{%0,%1,%2,%3}, {%4,%5,%6,%7}, {%8,%9}, {%0,%1,%2,%3};\n"
                 : "+f"(d[0]), "+f"(d[1]), "+f"(d[2]), "+f"(d[3])
                 : "r"(a[0]), "r"(a[1]), "r"(a[2]), "r"(a[3]), "r"(b[0]), "r"(b[1]));
}
__device__ __forceinline__ void cp16(u32 dst, const void* src) {
    asm volatile("cp.async.cg.shared.global [%0], [%1], 16;" :: "r"(dst), "l"(src));
}
#define CP_COMMIT() asm volatile("cp.async.commit_group;\n" ::: "memory")
#define CP_WAIT2()  asm volatile("cp.async.wait_group 2;\n" ::: "memory")

// ---------- mbarrier + bulk-copy helpers ----------
__device__ __forceinline__ void mbar_init(u32 mbar, u32 cnt) {
    asm volatile("mbarrier.init.shared.b64 [%0], %1;" :: "r"(mbar), "r"(cnt) : "memory");
}
__device__ __forceinline__ void mbar_expect(u32 mbar, u32 bytes) {
    asm volatile("mbarrier.arrive.expect_tx.shared.b64 _, [%0], %1;"
                 :: "r"(mbar), "r"(bytes) : "memory");
}
__device__ __forceinline__ void mbar_arrive(u32 mbar) {
    asm volatile("mbarrier.arrive.shared.b64 _, [%0];" :: "r"(mbar) : "memory");
}
__device__ __forceinline__ void bulk_g2s(u32 dst, const void* src, u32 bytes, u32 mbar) {
    asm volatile("cp.async.bulk.shared::cta.global.mbarrier::complete_tx::bytes "
                 "[%0], [%1], %2, [%3];"
                 :: "r"(dst), "l"(src), "r"(bytes), "r"(mbar) : "memory");
}
__device__ __forceinline__ void mbar_wait(u32 mbar, u32 parity) {
    asm volatile(
        "{\n\t"
        ".reg .pred P;\n\t"
        "WL%=:\n\t"
        "mbarrier.try_wait.parity.acquire.cta.shared::cta.b64 P, [%0], %1, 0x989680;\n\t"
        "@P bra WD%=;\n\t"
        "bra WL%=;\n\t"
        "WD%=:\n\t"
        "}"
        :: "r"(mbar), "r"(parity) : "memory");
}

// ---------- prep kernel 1: convert x + W_ih -> single fp16 ----------
__global__ void convert_inputs_kernel(const float* __restrict__ x,
                                      const float* __restrict__ W0,
                                      const float* __restrict__ Wr) {
    size_t i = (size_t)blockIdx.x * blockDim.x + threadIdx.x;
    const size_t NX = (size_t)Mc * K0P;
    if (i < NX) {
        int row = (int)(i / K0P), col = (int)(i - (size_t)row * K0P);
        float v = (col < 188) ? x[(size_t)row * 188 + col] : 0.f;
        g_x[i] = __float2half_rn(v);
    } else if (i < NX + WIH_ELEMS) {
        size_t j = i - NX;
        float v;
        if (j < (size_t)1536 * K0P) {
            int row = (int)(j / K0P), col = (int)(j - (size_t)row * K0P);
            v = (col < 188) ? W0[(size_t)row * 188 + col] : 0.f;
        } else {
            v = Wr[j - (size_t)1536 * K0P];
        }
        g_w[j] = __float2half_rn(v);
    }
}

// ---------- prep kernel 2: convert W_hh (swizzled K=32 chunks) + zero hsum ----------
constexpr size_t WHH_ELEMS = (size_t)16 * 768 * 256;
__global__ void convert_whh_zero_kernel(const float* __restrict__ Whh) {
    size_t i = (size_t)blockIdx.x * blockDim.x + threadIdx.x;
    if (i < (size_t)2 * Bc * Hc) g_hsum[i] = 0.f;
    if (i >= WHH_ELEMS) return;
    size_t l2 = i / ((size_t)768 * 256);
    size_t rem = i - l2 * 768 * 256;
    int n = (int)(rem / 256), k = (int)(rem % 256);
    float v = Whh[i];
    int kc = k >> 5;            // which 32-k chunk
    int kk = k & 31;
    u32 q = (u32)(kk >> 3);                      // 16B quadrant within 64B row
    u32 qp = q ^ (u32)((n >> 1) & 3);            // swizzle
    size_t byte_in = (size_t)n * 64 + qp * 16 + (size_t)(kk & 7) * 2;
    size_t o = ((size_t)l2 * 8 + (size_t)kc) * WCHUNK_E + byte_in / 2;
    g_whh[o] = __float2half_rn(v);
}

// ---------- input GEMM (tensor cores, single fp16, cp.async 4-stage) ----------
constexpr int GPITCH = 24;                  // fp16 elems per smem row (48B)
constexpr int GTSZ = 128 * GPITCH;          // elems per (stage,op) tile
constexpr int GSTAGES = 4;
constexpr int GEMM_SMEM = GSTAGES * 2 * GTSZ * 2; // 49152 B

__global__ void __launch_bounds__(256, 2) gemm_gx_mma(int layer, const float* __restrict__ bias) {
    extern __shared__ __half sm[];

    const __half *A, *W;
    int K;
    if (layer == 0) {
        A = g_x; W = g_w; K = K0P;
    } else {
        size_t wo = (size_t)1536 * K0P + (size_t)(layer - 1) * 1536 * 512;
        A = g_a; W = g_w + wo; K = 512;
    }

    const int tid = threadIdx.x;
    const int m0 = blockIdx.y * 128;
    const int n0 = blockIdx.x * 128;

    const int lrow = tid >> 1;
    const int lhalf = tid & 1;
    const size_t aoff = (size_t)(m0 + lrow) * K + lhalf * 8;
    const size_t boff = (size_t)(n0 + lrow) * K + lhalf * 8;
    const u32 smoffB = (u32)(lrow * GPITCH + lhalf * 8) * 2;   // bytes

    const int wid = tid >> 5, lane = tid & 31;
    const int wm = (wid & 1) << 6;
    const int wn = (wid >> 1) << 5;

    float acc[4][4][4];
#pragma unroll
    for (int mi = 0; mi < 4; mi++)
#pragma unroll
        for (int ni = 0; ni < 4; ni++)
#pragma unroll
            for (int e = 0; e < 4; e++) acc[mi][ni][e] = 0.f;

    const int lr = lane & 15, lh = lane >> 4;
    int aoffs[4], boffs[2];
#pragma unroll
    for (int mi = 0; mi < 4; mi++)
        aoffs[mi] = ((wm + mi * 16 + lr) * GPITCH + lh * 8) * 2;
#pragma unroll
    for (int p = 0; p < 2; p++)
        boffs[p] = ((wn + p * 16 + lr) * GPITCH + lh * 8) * 2;

    const u32 smb = smem_u32(sm);
    const int nk = K >> 4;
    constexpr u32 STB = 2 * GTSZ * 2;       // bytes per stage (A, W)

    auto load_chunk = [&](int kc, int s) {
        const size_t ka = (size_t)kc * 16;
        const u32 d = smb + (u32)s * STB + smoffB;
        cp16(d + 0 * GTSZ * 2, A + aoff + ka);
        cp16(d + 1 * GTSZ * 2, W + boff + ka);
    };

    // prologue: 3 chunks in flight
#pragma unroll
    for (int s = 0; s < GSTAGES - 1; s++) { load_chunk(s, s); CP_COMMIT(); }

#pragma unroll 1
    for (int kc = 0; kc < nk; kc++) {
        CP_WAIT2();                          // oldest (stage kc) complete; 2 in flight
        __syncthreads();                     // all warps done reading recycled stage
        if (kc + GSTAGES - 1 < nk) { load_chunk(kc + GSTAGES - 1, (kc + GSTAGES - 1) & 3); CP_COMMIT(); }

        const u32 sbase = smb + (u32)(kc & 3) * STB;
        u32 a[4][4], bw[4][2];
#pragma unroll
        for (int mi = 0; mi < 4; mi++)
            ldsm_x4(a[mi][0], a[mi][1], a[mi][2], a[mi][3], sbase + aoffs[mi]);
#pragma unroll
        for (int p = 0; p < 2; p++) {
            u32 t0, t1, t2, t3;
            ldsm_x4(t0, t1, t2, t3, sbase + boffs[p] + 1 * GTSZ * 2);
            bw[2 * p][0] = t0; bw[2 * p + 1][0] = t1;
            bw[2 * p][1] = t2; bw[2 * p + 1][1] = t3;
        }

#pragma unroll
        for (int mi = 0; mi < 4; mi++)
#pragma unroll
            for (int ni = 0; ni < 4; ni++)
                mma_f16(acc[mi][ni], a[mi], bw[ni]);
    }

    // epilogue: add bias, pack to fp16, scatter to gx[dir][m][g]
    const int cr = lane >> 2;
    const int cc = (lane & 3) << 1;
#pragma unroll
    for (int ni = 0; ni < 4; ni++) {
        const int n = n0 + wn + ni * 8 + cc;
        const int d = (n >= 768) ? 1 : 0;
        const int g = n - d * 768;
        const float bx = bias[n], by = bias[n + 1];
#pragma unroll
        for (int mi = 0; mi < 4; mi++) {
            const int m = m0 + wm + mi * 16 + cr;
            __half* p0 = g_gx + ((size_t)d * Mc + m) * 768 + g;
            *(u32*)p0 = cvt2h(acc[mi][ni][0] + bx, acc[mi][ni][1] + by);
            *(u32*)(p0 + 8 * 768) = cvt2h(acc[mi][ni][2] + bx, acc[mi][ni][3] + by);
        }
    }
}

// ---------- tensor-core GRU recurrence (K=32 chunks, mbarrier pipeline) ----------
constexpr int RROWS = 32;
constexpr int RTHREADS = 512;
constexpr int APITCH = 264;                 // fp16 elems per h-smem row
constexpr int NSTAGE = 3;
constexpr int HSM_E = RROWS * APITCH;       // h elems (single fp16)
constexpr int MBAR_OFF = NSTAGE * WCHUNK_B + HSM_E * 2;        // byte offset of mbars
constexpr int RECUR_SMEM = MBAR_OFF + 64;                      // ~161 KB

__global__ void __launch_bounds__(RTHREADS, 1) gru_recur_mma(
    const float* __restrict__ bhh_all, int layer)
{
    extern __shared__ __half rsm[];
    const int tid = threadIdx.x;
    const int w = tid >> 5, lane = tid & 31;
    const int dir = blockIdx.y;
    const int b0 = blockIdx.x * RROWS;
    const int l2 = layer * 2 + dir;
    const float* bhh = bhh_all + (size_t)l2 * 768;
    const __half* gxd = g_gx + (size_t)dir * Mc * 768;
    const __half* wsrc = g_whh + (size_t)l2 * 8 * WCHUNK_E;

    __half* hsm = rsm + NSTAGE * WCHUNK_E;
    const u32 smb = smem_u32(rsm);
    const u32 hsmb = smem_u32(hsm);
    const u32 mb_full  = smb + (u32)MBAR_OFF;        // 3 x 8B
    const u32 mb_empty = mb_full + NSTAGE * 8;       // 3 x 8B

    for (int i = tid; i < HSM_E; i += RTHREADS)
        hsm[i] = __ushort_as_half(0);
    if (tid == 0) {
#pragma unroll
        for (int s = 0; s < NSTAGE; s++) {
            mbar_init(mb_full + s * 8, 1);
            mbar_init(mb_empty + s * 8, 16);
        }
    }
    __syncthreads();
    // pre-charge: every warp marks all stages empty (completes empty phase 0)
    if (lane == 0) {
#pragma unroll
        for (int s = 0; s < NSTAGE; s++) mbar_arrive(mb_empty + s * 8);
    }
    __syncthreads();

    constexpr int NCHUNK = Tc * 8;           // 104 chunk iterations per layer
    auto issue = [&](int cc_) {
        if (cc_ < NCHUNK) {
            const int s2 = cc_ % NSTAGE;
            mbar_wait(mb_empty + s2 * 8, (u32)((cc_ / NSTAGE) & 1));
            mbar_expect(mb_full + s2 * 8, WCHUNK_B);
            bulk_g2s(smb + (u32)s2 * WCHUNK_B, wsrc + (size_t)(cc_ & 7) * WCHUNK_E,
                     WCHUNK_B, mb_full + s2 * 8);
        }
    };
    if (tid == 0) { issue(0); issue(1); }

    const int c2 = (lane & 3) << 1;   // col pair base within n8
    const int r1 = lane >> 2;         // row within m8 group
    const int lr = lane & 15, lh = lane >> 4;

    // precomputed ldsm base addresses
    u32 aoBase[2], bOff[3][2];
#pragma unroll
    for (int mt = 0; mt < 2; mt++)
        aoBase[mt] = (u32)(((mt * 16 + lr) * APITCH + lh * 8) * 2);
#pragma unroll
    for (int g = 0; g < 3; g++) {
        const u32 n = (u32)(g * 256 + w * 16 + lr);
        const u32 nx = (n >> 1) & 3;
#pragma unroll
        for (int j = 0; j < 2; j++)
            bOff[g][j] = n * 64 + ((((u32)(j * 2) + (u32)lh) ^ nx) << 4);
    }

    // recurrent biases for this thread's columns (per gate, per n8 sub-tile)
    float2 bh[3][2];
#pragma unroll
    for (int g = 0; g < 3; g++)
#pragma unroll
        for (int sub = 0; sub < 2; sub++)
            bh[g][sub] = *(const float2*)&bhh[g * 256 + w * 16 + sub * 8 + c2];

    // h (fp32) in C-fragment layout registers across steps
    float hprev[2][2][4];
#pragma unroll
    for (int mt = 0; mt < 2; mt++)
#pragma unroll
        for (int sub = 0; sub < 2; sub++)
#pragma unroll
            for (int e = 0; e < 4; e++) hprev[mt][sub][e] = 0.f;

    int c = 0;   // global chunk counter across steps

#pragma unroll 1
    for (int step = 0; step < Tc; step++) {
        const int tg = dir ? (Tc - 1 - step) : step;

        float acc[2][6][4];
#pragma unroll
        for (int mt = 0; mt < 2; mt++)
#pragma unroll
            for (int t = 0; t < 6; t++)
#pragma unroll
                for (int e = 0; e < 4; e++) acc[mt][t][e] = 0.f;

#pragma unroll 1
        for (int kc = 0; kc < 8; kc++) {
            if (tid == 0) issue(c + 2);
            const int s = c % NSTAGE;
            mbar_wait(mb_full + s * 8, (u32)((c / NSTAGE) & 1));

            // A fragments from h smem: 2 m16 tiles x 2 k16 groups
            const u32 akk = (u32)(kc * 64);
            u32 ah[2][2][4];
#pragma unroll
            for (int mt = 0; mt < 2; mt++)
#pragma unroll
                for (int j = 0; j < 2; j++)
                    ldsm_x4(ah[mt][j][0], ah[mt][j][1], ah[mt][j][2], ah[mt][j][3],
                            hsmb + aoBase[mt] + akk + (u32)(j * 32));

            const u32 sbase = smb + (u32)s * WCHUNK_B;
            u32 bfr[3][2][2][2];   // [gate][j][nt][reg]
#pragma unroll
            for (int g = 0; g < 3; g++)
#pragma unroll
                for (int j = 0; j < 2; j++) {
                    u32 t0, t1, t2, t3;
                    ldsm_x4(t0, t1, t2, t3, sbase + bOff[g][j]);
                    bfr[g][j][0][0] = t0; bfr[g][j][1][0] = t1;
                    bfr[g][j][0][1] = t2; bfr[g][j][1][1] = t3;
                }
            if (lane == 0) mbar_arrive(mb_empty + s * 8);   // warp done with stage s

#pragma unroll
            for (int j = 0; j < 2; j++)
#pragma unroll
                for (int g = 0; g < 3; g++)
#pragma unroll
                    for (int mt = 0; mt < 2; mt++)
#pragma unroll
                        for (int nt = 0; nt < 2; nt++)
                            mma_f16(acc[mt][g * 2 + nt], ah[mt][j], bfr[g][j][nt]);
            c++;
        }

        // gate math entirely in registers (gx loaded as fp16 pairs)
#pragma unroll
        for (int mt = 0; mt < 2; mt++)
#pragma unroll
            for (int sub = 0; sub < 2; sub++) {
                const int jc = w * 16 + sub * 8 + c2;
                const float2 br = bh[0][sub], bz = bh[1][sub], bn = bh[2][sub];
#pragma unroll
                for (int half = 0; half < 2; half++) {
                    const int row = mt * 16 + r1 + half * 8;
                    const int b = b0 + row;
                    const __half* gxrow = gxd + ((size_t)b * Tc + tg) * 768 + jc;
                    const float2 xr = h2f2(*(const u32*)gxrow);
                    const float2 xz = h2f2(*(const u32*)(gxrow + 256));
                    const float2 xn = h2f2(*(const u32*)(gxrow + 512));
                    const int e = half * 2;
                    float rx = sigf(xr.x + acc[mt][sub][e]     + br.x);
                    float ry = sigf(xr.y + acc[mt][sub][e + 1] + br.y);
                    float zx = sigf(xz.x + acc[mt][2 + sub][e]     + bz.x);
                    float zy = sigf(xz.y + acc[mt][2 + sub][e + 1] + bz.y);
                    float nx = tanhfast(xn.x + rx * (acc[mt][4 + sub][e]     + bn.x));
                    float ny = tanhfast(xn.y + ry * (acc[mt][4 + sub][e + 1] + bn.y));
                    float hx = (1.f - zx) * nx + zx * hprev[mt][sub][e];
                    float hy = (1.f - zy) * ny + zy * hprev[mt][sub][e + 1];
                    hprev[mt][sub][e] = hx;
                    hprev[mt][sub][e + 1] = hy;
                }
            }

        __syncthreads();   // all warps done reading h smem this step

        // write new h (single fp16): smem (A layout) + g_a (+ hsum)
#pragma unroll
        for (int mt = 0; mt < 2; mt++)
#pragma unroll
            for (int sub = 0; sub < 2; sub++) {
                const int jc = w * 16 + sub * 8 + c2;
#pragma unroll
                for (int half = 0; half < 2; half++) {
                    const int row = mt * 16 + r1 + half * 8;
                    const int b = b0 + row;
                    const int e = half * 2;
                    const float hx = hprev[mt][sub][e];
                    const float hy = hprev[mt][sub][e + 1];
                    const u32 ph = cvt2h(hx, hy);
                    *(u32*)(hsm + row * APITCH + jc) = ph;
                    const size_t ob = ((size_t)b * Tc + tg) * 512 + dir * 256 + jc;
                    *(u32*)(g_a + ob) = ph;
                    if (step == Tc - 1) {
                        float* hp = g_hsum + ((size_t)dir * Bc + b) * 256 + jc;
                        float2 cur = *(const float2*)hp;
                        cur.x += hx; cur.y += hy;
                        *(float2*)hp = cur;
                    }
                }
            }
        __syncthreads();   // h writes visible before next step's A ldsm
    }
}

// ---------- head: mean over 16 finals -> silu MLP -> scalar ----------
__global__ void head_kernel(const float* __restrict__ W1, const float* __restrict__ b1,
                            const float* __restrict__ W2, const float* __restrict__ b2,
                            const float* __restrict__ Wc, const float* __restrict__ bc,
                            float* __restrict__ out)
{
    const int b = blockIdx.x;
    const int tid = threadIdx.x;   // 64 threads
    __shared__ float hs[256];
    __shared__ float s1[64];
    for (int i = tid; i < 256; i += 64)
        hs[i] = (g_hsum[(size_t)b * 256 + i] + g_hsum[(size_t)(Bc + b) * 256 + i]) * (1.f / 16.f);
    __syncthreads();
    float a1 = b1[tid];
    const float* w1r = W1 + (size_t)tid * 256;
#pragma unroll 4
    for (int k = 0; k < 256; k++) a1 += hs[k] * w1r[k];
    s1[tid] = a1 * sigmf(a1);
    __syncthreads();
    if (tid < 32) {
        float a2 = b2[tid];
        const float* w2r = W2 + (size_t)tid * 64;
#pragma unroll
        for (int k = 0; k < 64; k++) a2 += s1[k] * w2r[k];
        float y = a2 * sigmf(a2);
        float v = y * Wc[tid];
#pragma unroll
        for (int o = 16; o > 0; o >>= 1) v += __shfl_down_sync(0xffffffffu, v, o);
        if (tid == 0) out[b] = v + bc[0];
    }
}

// ---------- launch ----------
extern "C" void kernel_launch(void* const* d_in, const int* in_sizes, int n_in,
                              void* d_out, int out_size) {
    (void)in_sizes; (void)n_in; (void)out_size;
    const float* x         = (const float*)d_in[0];
    const float* W_ih0     = (const float*)d_in[1];
    const float* W_ih_rest = (const float*)d_in[2];
    const float* W_hh      = (const float*)d_in[3];
    const float* b_ih      = (const float*)d_in[4];
    const float* b_hh      = (const float*)d_in[5];
    const float* W1        = (const float*)d_in[6];
    const float* b1        = (const float*)d_in[7];
    const float* W2        = (const float*)d_in[8];
    const float* b2        = (const float*)d_in[9];
    const float* Wc        = (const float*)d_in[10];
    const float* bc        = (const float*)d_in[11];
    float* out = (float*)d_out;

    cudaFuncSetAttribute(gemm_gx_mma,
                         cudaFuncAttributeMaxDynamicSharedMemorySize, GEMM_SMEM);
    cudaFuncSetAttribute(gru_recur_mma,
                         cudaFuncAttributeMaxDynamicSharedMemorySize, RECUR_SMEM);

    // 2 prep launches -> ncu's captured launch (index 3) = gru_recur_mma layer 0.
    const size_t NPREP1 = (size_t)Mc * K0P + WIH_ELEMS;
    convert_inputs_kernel<<<(int)((NPREP1 + 255) / 256), 256>>>(x, W_ih0, W_ih_rest);
    convert_whh_zero_kernel<<<(int)((WHH_ELEMS + 255) / 256), 256>>>(W_hh);

    dim3 ggrid(12, 208);            // N/128, M/128
    dim3 rgrid(Bc / RROWS, 2);      // 64 x 2 dirs

    for (int l = 0; l < 8; l++) {
        gemm_gx_mma<<<ggrid, 256, GEMM_SMEM>>>(l, b_ih + (size_t)l * 1536);
        gru_recur_mma<<<rgrid, RTHREADS, RECUR_SMEM>>>(b_hh, l);
    }

    head_kernel<<<Bc, 64>>>(W1, b1, W2, b2, Wc, bc, out);
}